// round 10
// baseline (speedup 1.0000x reference)
#include <cuda_runtime.h>
#include <cuda_bf16.h>
#include <math.h>
#include <stdint.h>

#define NMAX    100000
#define EMBC    300
#define F4      75
#define KP      304         // padded K: 19 k16 tiles
#define U4A     76          // uint4s per packed A row: 304/4
#define NPAD    320         // padded N (output cols)
#define NKT     19
#define NGMAX   4096
#define NLAYER  5
#define EMAX    200000

// ---------------- device scratch ----------------
__device__ __align__(16) unsigned g_aggx[(size_t)NMAX * KP];    // packed (hi|lo<<16) bf16
__device__ __align__(16) float    g_h   [(size_t)NMAX * EMBC];  // fp32 activations
__device__ __align__(16) unsigned g_wx  [NPAD * KP];            // g_wx[n*KP+k] = split(W[k][n])
__device__ float g_s[NMAX];
__device__ float g_colsum[EMBC];
__device__ float g_colsumsq[EMBC];
__device__ float g_scale[EMBC];
__device__ float g_shift[EMBC];
__device__ __align__(16) float g_hg[(size_t)NGMAX * EMBC];
__device__ __align__(16) float g_t [(size_t)NGMAX * 128];
__device__ int g_deg[NMAX];
__device__ int g_cursor[NMAX];
__device__ int g_row_ptr[NMAX + 1];
__device__ int g_csr_src[EMAX];
__device__ int g_csr_code[EMAX];

#define SEL_EXT  0
#define SEL_HG   2
#define SEL_T    4
__device__ __forceinline__ float* sel_ptr(int sel, float* ext)
{
    switch (sel) {
        case SEL_HG: return g_hg;
        case SEL_T:  return g_t;
        default:     return ext;
    }
}

// ---------------- split-bf16 helpers ----------------
__device__ __forceinline__ unsigned splitw(float v)
{
    __nv_bfloat16 h = __float2bfloat16(v);
    __nv_bfloat16 l = __float2bfloat16(v - __bfloat162float(h));
    return (unsigned)__bfloat16_as_ushort(h) | ((unsigned)__bfloat16_as_ushort(l) << 16);
}

// ---------------- smem helpers ----------------
__device__ __forceinline__ uint32_t smem_u32(const void* p)
{
    uint32_t a;
    asm("{ .reg .u64 t; cvta.to.shared.u64 t, %1; cvt.u32.u64 %0, t; }" : "=r"(a) : "l"(p));
    return a;
}
__device__ __forceinline__ void sts64(uint32_t addr, unsigned a, unsigned b)
{
    asm volatile("st.shared.v2.u32 [%0], {%1,%2};" :: "r"(addr), "r"(a), "r"(b) : "memory");
}
__device__ __forceinline__ void ldsm_x4(uint32_t* r, uint32_t addr)
{
    asm volatile("ldmatrix.sync.aligned.m8n8.x4.shared.b16 {%0,%1,%2,%3}, [%4];"
                 : "=r"(r[0]), "=r"(r[1]), "=r"(r[2]), "=r"(r[3]) : "r"(addr));
}
__device__ __forceinline__ void mma_bf16(float* c, const uint32_t* a, const uint32_t* b)
{
    asm volatile("mma.sync.aligned.m16n8k16.row.col.f32.bf16.bf16.f32 "
                 "{%0,%1,%2,%3}, {%4,%5,%6,%7}, {%8,%9}, {%0,%1,%2,%3};"
                 : "+f"(c[0]), "+f"(c[1]), "+f"(c[2]), "+f"(c[3])
                 : "r"(a[0]), "r"(a[1]), "r"(a[2]), "r"(a[3]), "r"(b[0]), "r"(b[1]));
}

// ================= CSR build =================
__global__ void k_zero2(int n)
{
    int i = blockIdx.x * blockDim.x + threadIdx.x;
    if (i < n) { g_deg[i] = 0; g_cursor[i] = 0; }
}
__global__ void k_count(const int* __restrict__ ei, int nE)
{
    int e = blockIdx.x * blockDim.x + threadIdx.x;
    if (e < nE) atomicAdd(&g_deg[ei[nE + e]], 1);
}
__global__ void k_scan(int n)
{
    __shared__ int sh[1024];
    int t = threadIdx.x;
    int chunk = (n + 1023) / 1024;
    int lo = t * chunk, hi = min(lo + chunk, n);
    int s = 0;
    for (int i = lo; i < hi; i++) s += g_deg[i];
    sh[t] = s;
    __syncthreads();
    for (int d = 1; d < 1024; d <<= 1) {
        int v = (t >= d) ? sh[t - d] : 0;
        __syncthreads();
        sh[t] += v;
        __syncthreads();
    }
    int run = sh[t] - s;
    for (int i = lo; i < hi; i++) { g_row_ptr[i] = run; run += g_deg[i]; }
    if (t == 1023) g_row_ptr[n] = run;
}
__global__ void k_fill(const int* __restrict__ ei, const int* __restrict__ et,
                       const int* __restrict__ ed, int nE)
{
    int e = blockIdx.x * blockDim.x + threadIdx.x;
    if (e >= nE) return;
    int c = ei[nE + e];
    int p = g_row_ptr[c] + atomicAdd(&g_cursor[c], 1);
    g_csr_src[p] = ei[e];
    g_csr_code[p] = et[e] * 3 + ed[e];
}

// ================= init: g_h = emb1[at] + emb2[ch] (fp32) =================
__global__ void k_init(const int* __restrict__ at, const int* __restrict__ ch,
                       const float* __restrict__ e1, const float* __restrict__ e2, int n)
{
    int idx = blockIdx.x * blockDim.x + threadIdx.x;
    if (idx >= n * F4) return;
    int i = idx / F4, c = idx % F4;
    float4 a = ((const float4*)e1)[(size_t)at[i] * F4 + c];
    float4 b = ((const float4*)e2)[(size_t)ch[i] * F4 + c];
    ((float4*)g_h)[idx] = make_float4(a.x + b.x, a.y + b.y, a.z + b.z, a.w + b.w);
}

// ================= per-layer: s[i] from CSR; zero col stats =================
__global__ void k_sconst(const float* __restrict__ ee1l, const float* __restrict__ ee2l, int n)
{
    int i = blockIdx.x * blockDim.x + threadIdx.x;
    if (i < n) {
        float base = ee1l[4] + ee2l[0];
        int p0 = g_row_ptr[i], p1 = g_row_ptr[i + 1];
        for (int p = p0; p < p1; p++) {
            int code = g_csr_code[p];
            base += ee1l[code / 3] + ee2l[code % 3];
        }
        g_s[i] = base;
    }
    if (i < EMBC) { g_colsum[i] = 0.f; g_colsumsq[i] = 0.f; }
}

// ================= BN scale/shift from stats =================
__global__ void k_mkscale(const float* __restrict__ gamma, const float* __restrict__ beta, int n)
{
    int i = threadIdx.x + blockIdx.x * blockDim.x;
    if (i >= EMBC) return;
    float inv_n = 1.f / (float)n;
    float mean = g_colsum[i] * inv_n;
    float var  = g_colsumsq[i] * inv_n - mean * mean;
    float sc = gamma[i] * rsqrtf(var + 1e-5f);
    g_scale[i] = sc;
    g_shift[i] = beta[i] - mean * sc;
}

// ================= W transpose + split =================
__global__ void k_wprep(const float* __restrict__ Wl)
{
    int idx = blockIdx.x * blockDim.x + threadIdx.x;
    if (idx >= NPAD * U4A) return;
    int nrow = idx / U4A, u = idx % U4A;
    unsigned w[4];
    #pragma unroll
    for (int j = 0; j < 4; j++) {
        int k = u * 4 + j;
        float v = (nrow < EMBC && k < EMBC) ? Wl[(size_t)k * EMBC + nrow] : 0.f;
        w[j] = splitw(v);
    }
    ((uint4*)g_wx)[idx] = make_uint4(w[0], w[1], w[2], w[3]);
}

// ======= fused gather: aggx[i] = split( T(h[i]) + sum_in T(h[src]) ) ========
__global__ void k_gather2(int n, int mode)
{
    int idx = blockIdx.x * blockDim.x + threadIdx.x;
    if (idx >= n * U4A) return;
    int i = idx / U4A, c = idx % U4A;
    if (c >= F4) { ((uint4*)g_aggx)[idx] = make_uint4(0, 0, 0, 0); return; }
    int f = c * 4;
    float4 sc = make_float4(1.f, 1.f, 1.f, 1.f);
    float4 sh = make_float4(0.f, 0.f, 0.f, 0.f);
    if (mode) {
        sc = *(const float4*)&g_scale[f];
        sh = *(const float4*)&g_shift[f];
    }
    float4 x = *(const float4*)&g_h[(size_t)i * EMBC + f];
    float v0, v1, v2, v3;
    if (mode) {
        v0 = fmaxf(fmaf(x.x, sc.x, sh.x), 0.f); v1 = fmaxf(fmaf(x.y, sc.y, sh.y), 0.f);
        v2 = fmaxf(fmaf(x.z, sc.z, sh.z), 0.f); v3 = fmaxf(fmaf(x.w, sc.w, sh.w), 0.f);
    } else { v0 = x.x; v1 = x.y; v2 = x.z; v3 = x.w; }
    int p0 = g_row_ptr[i], p1 = g_row_ptr[i + 1];
    for (int p = p0; p < p1; p++) {
        float4 y = *(const float4*)&g_h[(size_t)g_csr_src[p] * EMBC + f];
        if (mode) {
            v0 += fmaxf(fmaf(y.x, sc.x, sh.x), 0.f); v1 += fmaxf(fmaf(y.y, sc.y, sh.y), 0.f);
            v2 += fmaxf(fmaf(y.z, sc.z, sh.z), 0.f); v3 += fmaxf(fmaf(y.w, sc.w, sh.w), 0.f);
        } else { v0 += y.x; v1 += y.y; v2 += y.z; v3 += y.w; }
    }
    uint4 o;
    o.x = splitw(v0); o.y = splitw(v1); o.z = splitw(v2); o.w = splitw(v3);
    ((uint4*)g_aggx)[idx] = o;
}

// ================= HMMA split-bf16 GEMM + fused column stats ================
// grid = (nb=5, mb); nb fastest so the 5 CTAs sharing an A-tile co-run (L2 reuse)
// Fragment loads via ldmatrix.x4 (8 per warp-ktile instead of 32 lds32).
#define SBUF 18432

__global__ void __launch_bounds__(256)
k_gemm_mma(const float* __restrict__ bias, int M)
{
    __shared__ __align__(16) char smem[2 * SBUF];
    __shared__ float s_sum[64], s_sq[64];
    uint32_t sb = smem_u32(smem);
    int tid = threadIdx.x, lane = tid & 31, wid = tid >> 5;
    int wm = wid & 3, wn = wid >> 2;
    int m0 = blockIdx.y * 128, n0 = blockIdx.x * 64;
    const uint4* AG = (const uint4*)g_aggx;
    const uint4* WG = (const uint4*)g_wx;

    int ar0 = tid >> 2, au = tid & 3;
    int br0 = tid >> 2;

    float acc[2][4][4] = {};
    uint4 pa0, pa1, pb;

    pa0 = (m0 + ar0      < M) ? AG[(size_t)(m0 + ar0)      * U4A + au] : make_uint4(0,0,0,0);
    pa1 = (m0 + ar0 + 64 < M) ? AG[(size_t)(m0 + ar0 + 64) * U4A + au] : make_uint4(0,0,0,0);
    pb  = WG[(size_t)(n0 + br0) * U4A + au];
    {
        uint32_t base = sb;
        sts64(base +         ar0 * 48 + au * 8,        __byte_perm(pa0.x, pa0.y, 0x5410), __byte_perm(pa0.z, pa0.w, 0x5410));
        sts64(base + 6144 +  ar0 * 48 + au * 8,        __byte_perm(pa0.x, pa0.y, 0x7632), __byte_perm(pa0.z, pa0.w, 0x7632));
        sts64(base +         (ar0 + 64) * 48 + au * 8, __byte_perm(pa1.x, pa1.y, 0x5410), __byte_perm(pa1.z, pa1.w, 0x5410));
        sts64(base + 6144 +  (ar0 + 64) * 48 + au * 8, __byte_perm(pa1.x, pa1.y, 0x7632), __byte_perm(pa1.z, pa1.w, 0x7632));
        sts64(base + 12288 + br0 * 48 + au * 8,        __byte_perm(pb.x, pb.y, 0x5410),   __byte_perm(pb.z, pb.w, 0x5410));
        sts64(base + 15360 + br0 * 48 + au * 8,        __byte_perm(pb.x, pb.y, 0x7632),   __byte_perm(pb.z, pb.w, 0x7632));
    }
    if (tid < 64) { s_sum[tid] = 0.f; s_sq[tid] = 0.f; }
    __syncthreads();

    // ldmatrix per-lane address offsets (within a plane)
    int r8 = lane & 7, sub = lane >> 3;
    // A x4 tile (mt): mats {m-lo/k-lo, m-hi/k-lo, m-lo/k-hi, m-hi/k-hi}
    uint32_t aoffm[2];
    #pragma unroll
    for (int mt = 0; mt < 2; mt++)
        aoffm[mt] = (uint32_t)((wm * 32 + mt * 16 + (sub & 1) * 8 + r8) * 48 + (sub >> 1) * 16);
    // B x4 tile (nt-pair p): mats {nt=2p k-lo, nt=2p k-hi, nt=2p+1 k-lo, nt=2p+1 k-hi}
    uint32_t boffp[2];
    #pragma unroll
    for (int p = 0; p < 2; p++)
        boffp[p] = (uint32_t)((wn * 32 + p * 16 + (sub >> 1) * 8 + r8) * 48 + (sub & 1) * 16);

    for (int kt = 0; kt < NKT; kt++) {
        int b = kt & 1;
        if (kt < NKT - 1) {
            int kc = (kt + 1) * 4 + au;
            pa0 = (m0 + ar0      < M) ? AG[(size_t)(m0 + ar0)      * U4A + kc] : make_uint4(0,0,0,0);
            pa1 = (m0 + ar0 + 64 < M) ? AG[(size_t)(m0 + ar0 + 64) * U4A + kc] : make_uint4(0,0,0,0);
            pb  = WG[(size_t)(n0 + br0) * U4A + kc];
        }
        {
            uint32_t base = sb + b * SBUF;
            uint32_t af[2][2][4];      // [mt][plane][4]
            uint32_t bh[2][4], bl[2][4];   // [nt-pair][4] = {b0 ntE, b1 ntE, b0 ntO, b1 ntO}
            ldsm_x4(af[0][0], base +         aoffm[0]);
            ldsm_x4(af[1][0], base +         aoffm[1]);
            ldsm_x4(af[0][1], base + 6144 +  aoffm[0]);
            ldsm_x4(af[1][1], base + 6144 +  aoffm[1]);
            ldsm_x4(bh[0],    base + 12288 + boffp[0]);
            ldsm_x4(bh[1],    base + 12288 + boffp[1]);
            ldsm_x4(bl[0],    base + 15360 + boffp[0]);
            ldsm_x4(bl[1],    base + 15360 + boffp[1]);
            #pragma unroll
            for (int mt = 0; mt < 2; mt++)
                #pragma unroll
                for (int nt = 0; nt < 4; nt++) {
                    const uint32_t* bhf = &bh[nt >> 1][(nt & 1) * 2];
                    const uint32_t* blf = &bl[nt >> 1][(nt & 1) * 2];
                    mma_bf16(acc[mt][nt], af[mt][0], bhf);
                    mma_bf16(acc[mt][nt], af[mt][0], blf);
                    mma_bf16(acc[mt][nt], af[mt][1], bhf);
                }
        }
        if (kt < NKT - 1) {
            uint32_t base = sb + (b ^ 1) * SBUF;
            sts64(base +         ar0 * 48 + au * 8,        __byte_perm(pa0.x, pa0.y, 0x5410), __byte_perm(pa0.z, pa0.w, 0x5410));
            sts64(base + 6144 +  ar0 * 48 + au * 8,        __byte_perm(pa0.x, pa0.y, 0x7632), __byte_perm(pa0.z, pa0.w, 0x7632));
            sts64(base +         (ar0 + 64) * 48 + au * 8, __byte_perm(pa1.x, pa1.y, 0x5410), __byte_perm(pa1.z, pa1.w, 0x5410));
            sts64(base + 6144 +  (ar0 + 64) * 48 + au * 8, __byte_perm(pa1.x, pa1.y, 0x7632), __byte_perm(pa1.z, pa1.w, 0x7632));
            sts64(base + 12288 + br0 * 48 + au * 8,        __byte_perm(pb.x, pb.y, 0x5410),   __byte_perm(pb.z, pb.w, 0x5410));
            sts64(base + 15360 + br0 * 48 + au * 8,        __byte_perm(pb.x, pb.y, 0x7632),   __byte_perm(pb.z, pb.w, 0x7632));
        }
        __syncthreads();
    }

    // ---- epilogue: C + bias + s[row] -> g_h ; fused column stats ----
    float ls[4][2] = {}, lq[4][2] = {};
    #pragma unroll
    for (int mt = 0; mt < 2; mt++) {
        int row0 = m0 + wm * 32 + mt * 16 + (lane >> 2);
        int row1 = row0 + 8;
        float s0 = (row0 < M) ? g_s[row0] : 0.f;
        float s1 = (row1 < M) ? g_s[row1] : 0.f;
        #pragma unroll
        for (int nt = 0; nt < 4; nt++) {
            int col = n0 + wn * 32 + nt * 8 + (lane & 3) * 2;
            if (col < EMBC) {
                float b0 = bias[col], b1 = bias[col + 1];
                if (row0 < M) {
                    float v0 = acc[mt][nt][0] + b0 + s0;
                    float v1 = acc[mt][nt][1] + b1 + s0;
                    g_h[(size_t)row0 * EMBC + col]     = v0;
                    g_h[(size_t)row0 * EMBC + col + 1] = v1;
                    ls[nt][0] += v0; lq[nt][0] += v0 * v0;
                    ls[nt][1] += v1; lq[nt][1] += v1 * v1;
                }
                if (row1 < M) {
                    float v0 = acc[mt][nt][2] + b0 + s1;
                    float v1 = acc[mt][nt][3] + b1 + s1;
                    g_h[(size_t)row1 * EMBC + col]     = v0;
                    g_h[(size_t)row1 * EMBC + col + 1] = v1;
                    ls[nt][0] += v0; lq[nt][0] += v0 * v0;
                    ls[nt][1] += v1; lq[nt][1] += v1 * v1;
                }
            }
        }
    }
    #pragma unroll
    for (int nt = 0; nt < 4; nt++)
        #pragma unroll
        for (int jj = 0; jj < 2; jj++) {
            #pragma unroll
            for (int o = 4; o < 32; o <<= 1) {
                ls[nt][jj] += __shfl_xor_sync(0xffffffffu, ls[nt][jj], o);
                lq[nt][jj] += __shfl_xor_sync(0xffffffffu, lq[nt][jj], o);
            }
        }
    if (lane < 4) {
        #pragma unroll
        for (int nt = 0; nt < 4; nt++)
            #pragma unroll
            for (int jj = 0; jj < 2; jj++) {
                int ci = wn * 32 + nt * 8 + lane * 2 + jj;
                atomicAdd(&s_sum[ci], ls[nt][jj]);
                atomicAdd(&s_sq[ci],  lq[nt][jj]);
            }
    }
    __syncthreads();
    if (tid < 64) {
        int col = n0 + tid;
        if (col < EMBC) {
            atomicAdd(&g_colsum[col],   s_sum[tid]);
            atomicAdd(&g_colsumsq[col], s_sq[tid]);
        }
    }
}

// ================= final-layer norm (no relu), in place ================
__global__ void k_normfinal(int n)
{
    int idx = blockIdx.x * blockDim.x + threadIdx.x;
    if (idx >= n * F4) return;
    int f = (idx % F4) * 4;
    float4 sc = *(const float4*)&g_scale[f];
    float4 sh = *(const float4*)&g_shift[f];
    float4 x = ((float4*)g_h)[idx];
    ((float4*)g_h)[idx] = make_float4(fmaf(x.x, sc.x, sh.x), fmaf(x.y, sc.y, sh.y),
                                      fmaf(x.z, sc.z, sh.z), fmaf(x.w, sc.w, sh.w));
}

// ================= mean pool =================
__device__ __forceinline__ int lower_bound_i(const int* a, int n, int v)
{
    int lo = 0, hi = n;
    while (lo < hi) { int m = (lo + hi) >> 1; if (a[m] < v) lo = m + 1; else hi = m; }
    return lo;
}
__global__ void k_pool(const int* __restrict__ batch, int n)
{
    int g = blockIdx.x;
    int start = lower_bound_i(batch, n, g);
    int end   = lower_bound_i(batch, n, g + 1);
    int f = threadIdx.x;
    if (f >= EMBC) return;
    float s = 0.f;
    for (int i = start; i < end; i++)
        s += g_h[(size_t)i * EMBC + f];
    g_hg[(size_t)g * EMBC + f] = s / fmaxf((float)(end - start), 1.f);
}

// ================= SIMT sgemm for head =================
template<int EPI>
__global__ __launch_bounds__(256)
void k_sgemm(int a_sel, float* a_ext, const float* __restrict__ B,
             int c_sel, float* c_ext, int M, int N, int K,
             const float* __restrict__ bias)
{
    const float* A = sel_ptr(a_sel, a_ext);
    float*       C = sel_ptr(c_sel, c_ext);
    __shared__ __align__(16) float As[16][64];
    __shared__ __align__(16) float Bs[16][64];
    int tid = threadIdx.x;
    int tx = tid & 15, ty = tid >> 4;
    int m0 = blockIdx.x * 64, n0 = blockIdx.y * 64;
    int am = tid >> 2, ak4 = tid & 3;
    int bk = tid >> 4, bn4 = tid & 15;
    float acc[4][4] = {};
    for (int kt = 0; kt < K; kt += 16) {
        float4 av = make_float4(0.f, 0.f, 0.f, 0.f);
        int arow = m0 + am, acol = kt + ak4 * 4;
        if (arow < M && acol + 4 <= K)
            av = *(const float4*)(A + (size_t)arow * K + acol);
        As[ak4 * 4 + 0][am] = av.x;
        As[ak4 * 4 + 1][am] = av.y;
        As[ak4 * 4 + 2][am] = av.z;
        As[ak4 * 4 + 3][am] = av.w;
        float4 bv = make_float4(0.f, 0.f, 0.f, 0.f);
        int brow = kt + bk, bcol = n0 + bn4 * 4;
        if (brow < K && bcol + 4 <= N)
            bv = *(const float4*)(B + (size_t)brow * N + bcol);
        *(float4*)&Bs[bk][bn4 * 4] = bv;
        __syncthreads();
        #pragma unroll
        for (int k = 0; k < 16; k++) {
            float4 a4 = *(const float4*)&As[k][ty * 4];
            float4 b4 = *(const float4*)&Bs[k][tx * 4];
            float ar[4] = {a4.x, a4.y, a4.z, a4.w};
            float br[4] = {b4.x, b4.y, b4.z, b4.w};
            #pragma unroll
            for (int i = 0; i < 4; i++)
                #pragma unroll
                for (int j = 0; j < 4; j++)
                    acc[i][j] += ar[i] * br[j];
        }
        __syncthreads();
    }
    float bb[4];
    #pragma unroll
    for (int j = 0; j < 4; j++) {
        int col = n0 + tx * 4 + j;
        bb[j] = (col < N) ? bias[col] : 0.f;
    }
    #pragma unroll
    for (int i = 0; i < 4; i++) {
        int row = m0 + ty * 4 + i;
        if (row >= M) continue;
        #pragma unroll
        for (int j = 0; j < 4; j++) {
            int col = n0 + tx * 4 + j;
            if (col >= N) continue;
            float v = acc[i][j] + bb[j];
            if (EPI == 1)
                v = (v > 0.f) ? v + log1pf(expf(-v)) : log1pf(expf(v));
            C[(size_t)row * N + col] = v;
        }
    }
}

__global__ void k_pred(const float* __restrict__ W2, const float* __restrict__ b2,
                       float* __restrict__ out)
{
    int g = blockIdx.x;
    int w = threadIdx.x >> 5;
    int lane = threadIdx.x & 31;
    float s = 0.f;
    #pragma unroll
    for (int q = 0; q < 4; q++) {
        int i = lane * 4 + q;
        s += g_t[(size_t)g * 128 + i] * W2[i * 2 + w];
    }
    #pragma unroll
    for (int o = 16; o > 0; o >>= 1) s += __shfl_xor_sync(0xffffffffu, s, o);
    if (lane == 0) out[g * 2 + w] = s + b2[w];
}

// ======================================================================
extern "C" void kernel_launch(void* const* d_in, const int* in_sizes, int n_in,
                              void* d_out, int out_size)
{
    const int*   atom_type = (const int*)d_in[0];
    const int*   chirality = (const int*)d_in[1];
    const int*   edge_index= (const int*)d_in[2];
    const int*   edge_type = (const int*)d_in[3];
    const int*   edge_dir  = (const int*)d_in[4];
    const int*   batch     = (const int*)d_in[5];
    const float* atom_emb1 = (const float*)d_in[6];
    const float* atom_emb2 = (const float*)d_in[7];
    const float* W         = (const float*)d_in[8];
    const float* b         = (const float*)d_in[9];
    const float* ee1       = (const float*)d_in[10];
    const float* ee2       = (const float*)d_in[11];
    const float* bn_gamma  = (const float*)d_in[12];
    const float* bn_beta   = (const float*)d_in[13];
    const float* feat_W    = (const float*)d_in[14];
    const float* feat_b    = (const float*)d_in[15];
    const float* head_W1   = (const float*)d_in[16];
    const float* head_b1   = (const float*)d_in[17];
    const float* head_W2   = (const float*)d_in[18];
    const float* head_b2   = (const float*)d_in[19];

    int N  = in_sizes[0];
    int E  = in_sizes[3];
    int NG = out_size / (256 + 2);

    float* out_f = (float*)d_out;
    float* hf    = out_f;
    float* pred  = out_f + (size_t)NG * 256;

    // CSR build
    k_zero2<<<(N + 255) / 256, 256>>>(N);
    k_count<<<(E + 255) / 256, 256>>>(edge_index, E);
    k_scan<<<1, 1024>>>(N);
    k_fill<<<(E + 255) / 256, 256>>>(edge_index, edge_type, edge_dir, E);

    // embedding init (fp32 h)
    k_init<<<(N * F4 + 255) / 256, 256>>>(atom_type, chirality, atom_emb1, atom_emb2, N);

    dim3 ggrid(NPAD / 64, (N + 127) / 128);   // nb fastest -> A-tile L2 reuse
    for (int l = 0; l < NLAYER; l++) {
        const float* Wl   = W  + (size_t)l * EMBC * EMBC;
        const float* bl   = b  + (size_t)l * EMBC;
        const float* ee1l = ee1 + l * 5;
        const float* ee2l = ee2 + l * 3;

        if (l > 0)
            k_mkscale<<<2, 160>>>(bn_gamma + (l - 1) * EMBC, bn_beta + (l - 1) * EMBC, N);
        k_sconst<<<(N + 255) / 256, 256>>>(ee1l, ee2l, N);
        k_wprep<<<(NPAD * U4A + 255) / 256, 256>>>(Wl);
        k_gather2<<<(N * U4A + 255) / 256, 256>>>(N, l > 0 ? 1 : 0);
        k_gemm_mma<<<ggrid, 256>>>(bl, N);
    }

    k_mkscale<<<2, 160>>>(bn_gamma + (NLAYER - 1) * EMBC, bn_beta + (NLAYER - 1) * EMBC, N);
    k_normfinal<<<(N * F4 + 255) / 256, 256>>>(N);

    k_pool<<<NG, 320>>>(batch, N);
    {
        dim3 grid((NG + 63) / 64, (256 + 63) / 64);
        k_sgemm<0><<<grid, 256>>>(SEL_HG, nullptr, feat_W, SEL_EXT, hf,
                                  NG, 256, EMBC, feat_b);
    }
    {
        dim3 grid((NG + 63) / 64, (128 + 63) / 64);
        k_sgemm<1><<<grid, 256>>>(SEL_EXT, hf, head_W1, SEL_T, nullptr,
                                  NG, 128, 256, head_b1);
    }
    k_pred<<<NG, 64>>>(head_W2, head_b2, pred);
}

// round 11
// speedup vs baseline: 1.2826x; 1.2826x over previous
#include <cuda_runtime.h>
#include <cuda_bf16.h>
#include <cuda_fp16.h>
#include <math.h>
#include <stdint.h>

#define NMAX    100000
#define EMBC    300
#define F4      75
#define KP      304         // padded K: 19 k16 tiles
#define U4W     76          // uint4s per packed W row: 304/4
#define A_U4ROW 38          // uint4s per fp16 A row: 304 halves / 8
#define NPAD    320         // padded N (output cols)
#define NKT     19
#define NGMAX   4096
#define NLAYER  5
#define EMAX    200000

// ---------------- device scratch ----------------
__device__ __align__(16) unsigned short g_aggh[(size_t)NMAX * KP];  // fp16 gathered A
__device__ __align__(16) float    g_h   [(size_t)NMAX * EMBC];      // fp32 activations
__device__ __align__(16) unsigned g_wx  [NPAD * KP];                // (hi|lo<<16) fp16 of W^T
__device__ float g_s[NMAX];
__device__ float g_colsum[EMBC];
__device__ float g_colsumsq[EMBC];
__device__ float g_scale[EMBC];
__device__ float g_shift[EMBC];
__device__ __align__(16) float g_hg[(size_t)NGMAX * EMBC];
__device__ __align__(16) float g_t [(size_t)NGMAX * 128];
__device__ int g_deg[NMAX];
__device__ int g_cursor[NMAX];
__device__ int g_row_ptr[NMAX + 1];
__device__ int g_csr_src[EMAX];
__device__ int g_csr_code[EMAX];

#define SEL_EXT  0
#define SEL_HG   2
#define SEL_T    4
__device__ __forceinline__ float* sel_ptr(int sel, float* ext)
{
    switch (sel) {
        case SEL_HG: return g_hg;
        case SEL_T:  return g_t;
        default:     return ext;
    }
}

// ---------------- fp16 helpers ----------------
__device__ __forceinline__ unsigned splitw_h(float v)    // W: hi|lo fp16 split
{
    __half h = __float2half_rn(v);
    __half l = __float2half_rn(v - __half2float(h));
    return (unsigned)__half_as_ushort(h) | ((unsigned)__half_as_ushort(l) << 16);
}
__device__ __forceinline__ unsigned pack_h2(float a, float b)
{
    __half2 p = __floats2half2_rn(a, b);
    return *reinterpret_cast<unsigned*>(&p);
}

// ---------------- smem helpers ----------------
__device__ __forceinline__ uint32_t smem_u32(const void* p)
{
    uint32_t a;
    asm("{ .reg .u64 t; cvta.to.shared.u64 t, %1; cvt.u32.u64 %0, t; }" : "=r"(a) : "l"(p));
    return a;
}
__device__ __forceinline__ void sts64(uint32_t addr, unsigned a, unsigned b)
{
    asm volatile("st.shared.v2.u32 [%0], {%1,%2};" :: "r"(addr), "r"(a), "r"(b) : "memory");
}
__device__ __forceinline__ void sts128(uint32_t addr, uint4 v)
{
    asm volatile("st.shared.v4.u32 [%0], {%1,%2,%3,%4};"
                 :: "r"(addr), "r"(v.x), "r"(v.y), "r"(v.z), "r"(v.w) : "memory");
}
__device__ __forceinline__ uint32_t lds32(uint32_t addr)
{
    uint32_t v;
    asm volatile("ld.shared.b32 %0, [%1];" : "=r"(v) : "r"(addr));
    return v;
}
__device__ __forceinline__ void mma_f16(float* c, const uint32_t* a, const uint32_t* b)
{
    asm volatile("mma.sync.aligned.m16n8k16.row.col.f32.f16.f16.f32 "
                 "{%0,%1,%2,%3}, {%4,%5,%6,%7}, {%8,%9}, {%0,%1,%2,%3};"
                 : "+f"(c[0]), "+f"(c[1]), "+f"(c[2]), "+f"(c[3])
                 : "r"(a[0]), "r"(a[1]), "r"(a[2]), "r"(a[3]), "r"(b[0]), "r"(b[1]));
}

// ================= CSR build =================
__global__ void k_zero2(int n)
{
    int i = blockIdx.x * blockDim.x + threadIdx.x;
    if (i < n) { g_deg[i] = 0; g_cursor[i] = 0; }
}
__global__ void k_count(const int* __restrict__ ei, int nE)
{
    int e = blockIdx.x * blockDim.x + threadIdx.x;
    if (e < nE) atomicAdd(&g_deg[ei[nE + e]], 1);
}
__global__ void k_scan(int n)
{
    __shared__ int sh[1024];
    int t = threadIdx.x;
    int chunk = (n + 1023) / 1024;
    int lo = t * chunk, hi = min(lo + chunk, n);
    int s = 0;
    for (int i = lo; i < hi; i++) s += g_deg[i];
    sh[t] = s;
    __syncthreads();
    for (int d = 1; d < 1024; d <<= 1) {
        int v = (t >= d) ? sh[t - d] : 0;
        __syncthreads();
        sh[t] += v;
        __syncthreads();
    }
    int run = sh[t] - s;
    for (int i = lo; i < hi; i++) { g_row_ptr[i] = run; run += g_deg[i]; }
    if (t == 1023) g_row_ptr[n] = run;
}
__global__ void k_fill(const int* __restrict__ ei, const int* __restrict__ et,
                       const int* __restrict__ ed, int nE)
{
    int e = blockIdx.x * blockDim.x + threadIdx.x;
    if (e >= nE) return;
    int c = ei[nE + e];
    int p = g_row_ptr[c] + atomicAdd(&g_cursor[c], 1);
    g_csr_src[p] = ei[e];
    g_csr_code[p] = et[e] * 3 + ed[e];
}

// ================= init: g_h = emb1[at] + emb2[ch] (fp32) =================
__global__ void k_init(const int* __restrict__ at, const int* __restrict__ ch,
                       const float* __restrict__ e1, const float* __restrict__ e2, int n)
{
    int idx = blockIdx.x * blockDim.x + threadIdx.x;
    if (idx >= n * F4) return;
    int i = idx / F4, c = idx % F4;
    float4 a = ((const float4*)e1)[(size_t)at[i] * F4 + c];
    float4 b = ((const float4*)e2)[(size_t)ch[i] * F4 + c];
    ((float4*)g_h)[idx] = make_float4(a.x + b.x, a.y + b.y, a.z + b.z, a.w + b.w);
}

// ================= per-layer: s[i] from CSR; zero col stats =================
__global__ void k_sconst(const float* __restrict__ ee1l, const float* __restrict__ ee2l, int n)
{
    int i = blockIdx.x * blockDim.x + threadIdx.x;
    if (i < n) {
        float base = ee1l[4] + ee2l[0];
        int p0 = g_row_ptr[i], p1 = g_row_ptr[i + 1];
        for (int p = p0; p < p1; p++) {
            int code = g_csr_code[p];
            base += ee1l[code / 3] + ee2l[code % 3];
        }
        g_s[i] = base;
    }
    if (i < EMBC) { g_colsum[i] = 0.f; g_colsumsq[i] = 0.f; }
}

// ================= BN scale/shift from stats =================
__global__ void k_mkscale(const float* __restrict__ gamma, const float* __restrict__ beta, int n)
{
    int i = threadIdx.x + blockIdx.x * blockDim.x;
    if (i >= EMBC) return;
    float inv_n = 1.f / (float)n;
    float mean = g_colsum[i] * inv_n;
    float var  = g_colsumsq[i] * inv_n - mean * mean;
    float sc = gamma[i] * rsqrtf(var + 1e-5f);
    g_scale[i] = sc;
    g_shift[i] = beta[i] - mean * sc;
}

// ================= W transpose + fp16 split =================
__global__ void k_wprep(const float* __restrict__ Wl)
{
    int idx = blockIdx.x * blockDim.x + threadIdx.x;
    if (idx >= NPAD * U4W) return;
    int nrow = idx / U4W, u = idx % U4W;
    unsigned w[4];
    #pragma unroll
    for (int j = 0; j < 4; j++) {
        int k = u * 4 + j;
        float v = (nrow < EMBC && k < EMBC) ? Wl[(size_t)k * EMBC + nrow] : 0.f;
        w[j] = splitw_h(v);
    }
    ((uint4*)g_wx)[idx] = make_uint4(w[0], w[1], w[2], w[3]);
}

// ======= fused gather: aggh[i] = fp16( T(h[i]) + sum_in T(h[src]) ) =========
// mode 0: T = identity (layer 0). mode 1: T(x) = max(scale*x+shift, 0).
__global__ void k_gather2(int n, int mode)
{
    int idx = blockIdx.x * blockDim.x + threadIdx.x;
    if (idx >= n * U4W) return;
    int i = idx / U4W, c = idx % U4W;
    if (c >= F4) { ((uint2*)g_aggh)[idx] = make_uint2(0, 0); return; }
    int f = c * 4;
    float4 sc = make_float4(1.f, 1.f, 1.f, 1.f);
    float4 sh = make_float4(0.f, 0.f, 0.f, 0.f);
    if (mode) {
        sc = *(const float4*)&g_scale[f];
        sh = *(const float4*)&g_shift[f];
    }
    float4 x = *(const float4*)&g_h[(size_t)i * EMBC + f];
    float v0, v1, v2, v3;
    if (mode) {
        v0 = fmaxf(fmaf(x.x, sc.x, sh.x), 0.f); v1 = fmaxf(fmaf(x.y, sc.y, sh.y), 0.f);
        v2 = fmaxf(fmaf(x.z, sc.z, sh.z), 0.f); v3 = fmaxf(fmaf(x.w, sc.w, sh.w), 0.f);
    } else { v0 = x.x; v1 = x.y; v2 = x.z; v3 = x.w; }
    int p0 = g_row_ptr[i], p1 = g_row_ptr[i + 1];
    for (int p = p0; p < p1; p++) {
        float4 y = *(const float4*)&g_h[(size_t)g_csr_src[p] * EMBC + f];
        if (mode) {
            v0 += fmaxf(fmaf(y.x, sc.x, sh.x), 0.f); v1 += fmaxf(fmaf(y.y, sc.y, sh.y), 0.f);
            v2 += fmaxf(fmaf(y.z, sc.z, sh.z), 0.f); v3 += fmaxf(fmaf(y.w, sc.w, sh.w), 0.f);
        } else { v0 += y.x; v1 += y.y; v2 += y.z; v3 += y.w; }
    }
    uint2 o;
    o.x = pack_h2(v0, v1);
    o.y = pack_h2(v2, v3);
    ((uint2*)g_aggh)[idx] = o;
}

// ================= HMMA fp16 2-pass GEMM + fused column stats ================
// D = Ah * (Wh + Wl) : 16 mma per warp-ktile (was 24).
// smem per buffer: A 128x48 = 6144 | Bh 3072 | Bl 3072 = 12288 B.
// grid = (nb=5, mb); nb fastest so the 5 CTAs sharing an A-tile co-run (L2 reuse)
#define SBUF 12288

__global__ void __launch_bounds__(256)
k_gemm_mma(const float* __restrict__ bias, int M)
{
    __shared__ __align__(16) char smem[2 * SBUF];
    __shared__ float s_sum[64], s_sq[64];
    uint32_t sb = smem_u32(smem);
    int tid = threadIdx.x, lane = tid & 31, wid = tid >> 5;
    int wm = wid & 3, wn = wid >> 2;
    int m0 = blockIdx.y * 128, n0 = blockIdx.x * 64;
    const uint4* AGH = (const uint4*)g_aggh;   // 38 uint4 per row (fp16)
    const uint4* WG  = (const uint4*)g_wx;     // 76 uint4 per row (hi|lo packed)

    int arow = tid >> 1, apart = tid & 1;      // A copy: 128 rows x 2 x 16B
    int br0 = tid >> 2, au = tid & 3;          // B: 64 rows x 4 uint4

    float acc[2][4][4] = {};
    uint4 pa, pb;

    pa = (m0 + arow < M) ? AGH[(size_t)(m0 + arow) * A_U4ROW + apart] : make_uint4(0,0,0,0);
    pb = WG[(size_t)(n0 + br0) * U4W + au];
    {
        uint32_t base = sb;
        sts128(base + arow * 48 + apart * 16, pa);
        sts64(base + 6144 + br0 * 48 + au * 8, __byte_perm(pb.x, pb.y, 0x5410), __byte_perm(pb.z, pb.w, 0x5410));
        sts64(base + 9216 + br0 * 48 + au * 8, __byte_perm(pb.x, pb.y, 0x7632), __byte_perm(pb.z, pb.w, 0x7632));
    }
    if (tid < 64) { s_sum[tid] = 0.f; s_sq[tid] = 0.f; }
    __syncthreads();

    uint32_t aoff = (uint32_t)((wm * 32 + (lane >> 2)) * 48 + (lane & 3) * 4);
    uint32_t boff = (uint32_t)((wn * 32 + (lane >> 2)) * 48 + (lane & 3) * 4);

    for (int kt = 0; kt < NKT; kt++) {
        int b = kt & 1;
        if (kt < NKT - 1) {
            pa = (m0 + arow < M) ? AGH[(size_t)(m0 + arow) * A_U4ROW + (kt + 1) * 2 + apart]
                                 : make_uint4(0,0,0,0);
            pb = WG[(size_t)(n0 + br0) * U4W + (kt + 1) * 4 + au];
        }
        {
            uint32_t base = sb + b * SBUF;
            uint32_t AH = base + aoff;
            uint32_t BH = base + 6144 + boff, BL = base + 9216 + boff;
            uint32_t af[2][4], bh[4][2], bl[4][2];
            #pragma unroll
            for (int mt = 0; mt < 2; mt++) {
                uint32_t r = AH + mt * 16 * 48;
                af[mt][0] = lds32(r);       af[mt][1] = lds32(r + 8 * 48);
                af[mt][2] = lds32(r + 16);  af[mt][3] = lds32(r + 8 * 48 + 16);
            }
            #pragma unroll
            for (int nt = 0; nt < 4; nt++) {
                uint32_t r = BH + nt * 8 * 48;
                bh[nt][0] = lds32(r);  bh[nt][1] = lds32(r + 16);
                uint32_t q = BL + nt * 8 * 48;
                bl[nt][0] = lds32(q);  bl[nt][1] = lds32(q + 16);
            }
            #pragma unroll
            for (int mt = 0; mt < 2; mt++)
                #pragma unroll
                for (int nt = 0; nt < 4; nt++) {
                    mma_f16(acc[mt][nt], af[mt], bh[nt]);
                    mma_f16(acc[mt][nt], af[mt], bl[nt]);
                }
        }
        if (kt < NKT - 1) {
            uint32_t base = sb + (b ^ 1) * SBUF;
            sts128(base + arow * 48 + apart * 16, pa);
            sts64(base + 6144 + br0 * 48 + au * 8, __byte_perm(pb.x, pb.y, 0x5410), __byte_perm(pb.z, pb.w, 0x5410));
            sts64(base + 9216 + br0 * 48 + au * 8, __byte_perm(pb.x, pb.y, 0x7632), __byte_perm(pb.z, pb.w, 0x7632));
        }
        __syncthreads();
    }

    // ---- epilogue: C + bias + s[row] -> g_h ; fused column stats ----
    float ls[4][2] = {}, lq[4][2] = {};
    #pragma unroll
    for (int mt = 0; mt < 2; mt++) {
        int row0 = m0 + wm * 32 + mt * 16 + (lane >> 2);
        int row1 = row0 + 8;
        float s0 = (row0 < M) ? g_s[row0] : 0.f;
        float s1 = (row1 < M) ? g_s[row1] : 0.f;
        #pragma unroll
        for (int nt = 0; nt < 4; nt++) {
            int col = n0 + wn * 32 + nt * 8 + (lane & 3) * 2;
            if (col < EMBC) {
                float b0 = bias[col], b1 = bias[col + 1];
                if (row0 < M) {
                    float v0 = acc[mt][nt][0] + b0 + s0;
                    float v1 = acc[mt][nt][1] + b1 + s0;
                    g_h[(size_t)row0 * EMBC + col]     = v0;
                    g_h[(size_t)row0 * EMBC + col + 1] = v1;
                    ls[nt][0] += v0; lq[nt][0] += v0 * v0;
                    ls[nt][1] += v1; lq[nt][1] += v1 * v1;
                }
                if (row1 < M) {
                    float v0 = acc[mt][nt][2] + b0 + s1;
                    float v1 = acc[mt][nt][3] + b1 + s1;
                    g_h[(size_t)row1 * EMBC + col]     = v0;
                    g_h[(size_t)row1 * EMBC + col + 1] = v1;
                    ls[nt][0] += v0; lq[nt][0] += v0 * v0;
                    ls[nt][1] += v1; lq[nt][1] += v1 * v1;
                }
            }
        }
    }
    #pragma unroll
    for (int nt = 0; nt < 4; nt++)
        #pragma unroll
        for (int jj = 0; jj < 2; jj++) {
            #pragma unroll
            for (int o = 4; o < 32; o <<= 1) {
                ls[nt][jj] += __shfl_xor_sync(0xffffffffu, ls[nt][jj], o);
                lq[nt][jj] += __shfl_xor_sync(0xffffffffu, lq[nt][jj], o);
            }
        }
    if (lane < 4) {
        #pragma unroll
        for (int nt = 0; nt < 4; nt++)
            #pragma unroll
            for (int jj = 0; jj < 2; jj++) {
                int ci = wn * 32 + nt * 8 + lane * 2 + jj;
                atomicAdd(&s_sum[ci], ls[nt][jj]);
                atomicAdd(&s_sq[ci],  lq[nt][jj]);
            }
    }
    __syncthreads();
    if (tid < 64) {
        int col = n0 + tid;
        if (col < EMBC) {
            atomicAdd(&g_colsum[col],   s_sum[tid]);
            atomicAdd(&g_colsumsq[col], s_sq[tid]);
        }
    }
}

// ================= mean pool with fused final BN =================
__device__ __forceinline__ int lower_bound_i(const int* a, int n, int v)
{
    int lo = 0, hi = n;
    while (lo < hi) { int m = (lo + hi) >> 1; if (a[m] < v) lo = m + 1; else hi = m; }
    return lo;
}
__global__ void k_pool(const int* __restrict__ batch, int n)
{
    int g = blockIdx.x;
    int start = lower_bound_i(batch, n, g);
    int end   = lower_bound_i(batch, n, g + 1);
    int f = threadIdx.x;
    if (f >= EMBC) return;
    float s = 0.f;
    for (int i = start; i < end; i++)
        s += g_h[(size_t)i * EMBC + f];
    float m = s / fmaxf((float)(end - start), 1.f);
    g_hg[(size_t)g * EMBC + f] = fmaf(m, g_scale[f], g_shift[f]);
}

// ================= SIMT sgemm for head =================
template<int EPI>
__global__ __launch_bounds__(256)
void k_sgemm(int a_sel, float* a_ext, const float* __restrict__ B,
             int c_sel, float* c_ext, int M, int N, int K,
             const float* __restrict__ bias)
{
    const float* A = sel_ptr(a_sel, a_ext);
    float*       C = sel_ptr(c_sel, c_ext);
    __shared__ __align__(16) float As[16][64];
    __shared__ __align__(16) float Bs[16][64];
    int tid = threadIdx.x;
    int tx = tid & 15, ty = tid >> 4;
    int m0 = blockIdx.x * 64, n0 = blockIdx.y * 64;
    int am = tid >> 2, ak4 = tid & 3;
    int bk = tid >> 4, bn4 = tid & 15;
    float acc[4][4] = {};
    for (int kt = 0; kt < K; kt += 16) {
        float4 av = make_float4(0.f, 0.f, 0.f, 0.f);
        int arow = m0 + am, acol = kt + ak4 * 4;
        if (arow < M && acol + 4 <= K)
            av = *(const float4*)(A + (size_t)arow * K + acol);
        As[ak4 * 4 + 0][am] = av.x;
        As[ak4 * 4 + 1][am] = av.y;
        As[ak4 * 4 + 2][am] = av.z;
        As[ak4 * 4 + 3][am] = av.w;
        float4 bv = make_float4(0.f, 0.f, 0.f, 0.f);
        int brow = kt + bk, bcol = n0 + bn4 * 4;
        if (brow < K && bcol + 4 <= N)
            bv = *(const float4*)(B + (size_t)brow * N + bcol);
        *(float4*)&Bs[bk][bn4 * 4] = bv;
        __syncthreads();
        #pragma unroll
        for (int k = 0; k < 16; k++) {
            float4 a4 = *(const float4*)&As[k][ty * 4];
            float4 b4 = *(const float4*)&Bs[k][tx * 4];
            float ar[4] = {a4.x, a4.y, a4.z, a4.w};
            float br[4] = {b4.x, b4.y, b4.z, b4.w};
            #pragma unroll
            for (int i = 0; i < 4; i++)
                #pragma unroll
                for (int j = 0; j < 4; j++)
                    acc[i][j] += ar[i] * br[j];
        }
        __syncthreads();
    }
    float bb[4];
    #pragma unroll
    for (int j = 0; j < 4; j++) {
        int col = n0 + tx * 4 + j;
        bb[j] = (col < N) ? bias[col] : 0.f;
    }
    #pragma unroll
    for (int i = 0; i < 4; i++) {
        int row = m0 + ty * 4 + i;
        if (row >= M) continue;
        #pragma unroll
        for (int j = 0; j < 4; j++) {
            int col = n0 + tx * 4 + j;
            if (col >= N) continue;
            float v = acc[i][j] + bb[j];
            if (EPI == 1)
                v = (v > 0.f) ? v + log1pf(expf(-v)) : log1pf(expf(v));
            C[(size_t)row * N + col] = v;
        }
    }
}

__global__ void k_pred(const float* __restrict__ W2, const float* __restrict__ b2,
                       float* __restrict__ out)
{
    int g = blockIdx.x;
    int w = threadIdx.x >> 5;
    int lane = threadIdx.x & 31;
    float s = 0.f;
    #pragma unroll
    for (int q = 0; q < 4; q++) {
        int i = lane * 4 + q;
        s += g_t[(size_t)g * 128 + i] * W2[i * 2 + w];
    }
    #pragma unroll
    for (int o = 16; o > 0; o >>= 1) s += __shfl_xor_sync(0xffffffffu, s, o);
    if (lane == 0) out[g * 2 + w] = s + b2[w];
}

// ======================================================================
extern "C" void kernel_launch(void* const* d_in, const int* in_sizes, int n_in,
                              void* d_out, int out_size)
{
    const int*   atom_type = (const int*)d_in[0];
    const int*   chirality = (const int*)d_in[1];
    const int*   edge_index= (const int*)d_in[2];
    const int*   edge_type = (const int*)d_in[3];
    const int*   edge_dir  = (const int*)d_in[4];
    const int*   batch     = (const int*)d_in[5];
    const float* atom_emb1 = (const float*)d_in[6];
    const float* atom_emb2 = (const float*)d_in[7];
    const float* W         = (const float*)d_in[8];
    const float* b         = (const float*)d_in[9];
    const float* ee1       = (const float*)d_in[10];
    const float* ee2       = (const float*)d_in[11];
    const float* bn_gamma  = (const float*)d_in[12];
    const float* bn_beta   = (const float*)d_in[13];
    const float* feat_W    = (const float*)d_in[14];
    const float* feat_b    = (const float*)d_in[15];
    const float* head_W1   = (const float*)d_in[16];
    const float* head_b1   = (const float*)d_in[17];
    const float* head_W2   = (const float*)d_in[18];
    const float* head_b2   = (const float*)d_in[19];

    int N  = in_sizes[0];
    int E  = in_sizes[3];
    int NG = out_size / (256 + 2);

    float* out_f = (float*)d_out;
    float* hf    = out_f;
    float* pred  = out_f + (size_t)NG * 256;

    // CSR build
    k_zero2<<<(N + 255) / 256, 256>>>(N);
    k_count<<<(E + 255) / 256, 256>>>(edge_index, E);
    k_scan<<<1, 1024>>>(N);
    k_fill<<<(E + 255) / 256, 256>>>(edge_index, edge_type, edge_dir, E);

    // embedding init (fp32 h)
    k_init<<<(N * F4 + 255) / 256, 256>>>(atom_type, chirality, atom_emb1, atom_emb2, N);

    dim3 ggrid(NPAD / 64, (N + 127) / 128);   // nb fastest -> A-tile L2 reuse
    for (int l = 0; l < NLAYER; l++) {
        const float* Wl   = W  + (size_t)l * EMBC * EMBC;
        const float* bl   = b  + (size_t)l * EMBC;
        const float* ee1l = ee1 + l * 5;
        const float* ee2l = ee2 + l * 3;

        if (l > 0)
            k_mkscale<<<2, 160>>>(bn_gamma + (l - 1) * EMBC, bn_beta + (l - 1) * EMBC, N);
        k_sconst<<<(N + 255) / 256, 256>>>(ee1l, ee2l, N);
        k_wprep<<<(NPAD * U4W + 255) / 256, 256>>>(Wl);
        k_gather2<<<(N * U4W + 255) / 256, 256>>>(N, l > 0 ? 1 : 0);
        k_gemm_mma<<<ggrid, 256>>>(bl, N);
    }

    // final BN folded into pooling
    k_mkscale<<<2, 160>>>(bn_gamma + (NLAYER - 1) * EMBC, bn_beta + (NLAYER - 1) * EMBC, N);

    k_pool<<<NG, 320>>>(batch, N);
    {
        dim3 grid((NG + 63) / 64, (256 + 63) / 64);
        k_sgemm<0><<<grid, 256>>>(SEL_HG, nullptr, feat_W, SEL_EXT, hf,
                                  NG, 256, EMBC, feat_b);
    }
    {
        dim3 grid((NG + 63) / 64, (128 + 63) / 64);
        k_sgemm<1><<<grid, 256>>>(SEL_EXT, hf, head_W1, SEL_T, nullptr,
                                  NG, 128, 256, head_b1);
    }
    k_pred<<<NG, 64>>>(head_W2, head_b2, pred);
}

// round 12
// speedup vs baseline: 1.3487x; 1.0515x over previous
#include <cuda_runtime.h>
#include <cuda_bf16.h>
#include <cuda_fp16.h>
#include <math.h>
#include <stdint.h>

#define NMAX    100000
#define EMBC    300
#define F4      75
#define KP      304         // padded K: 19 k16 tiles
#define U4W     76          // legacy: uint4s per fp32-pair row (unused for W now)
#define A_U4ROW 38          // uint4s per fp16 A row: 304 halves / 8
#define W_U2ROW 76          // uint2s per fp16 W row: 304 halves / 4
#define NPAD    320         // padded N (output cols)
#define NKT     19
#define NGMAX   4096
#define NLAYER  5
#define EMAX    200000

// ---------------- device scratch ----------------
__device__ __align__(16) unsigned short g_aggh[(size_t)NMAX * KP];  // fp16 gathered A
__device__ __align__(16) float    g_h   [(size_t)NMAX * EMBC];      // fp32 activations
__device__ __align__(16) unsigned short g_wh[NPAD * KP];            // fp16 W^T
__device__ float g_s[NMAX];
__device__ float g_colsum[EMBC];
__device__ float g_colsumsq[EMBC];
__device__ float g_scale[EMBC];
__device__ float g_shift[EMBC];
__device__ __align__(16) float g_hg[(size_t)NGMAX * EMBC];
__device__ __align__(16) float g_t [(size_t)NGMAX * 128];
__device__ int g_deg[NMAX];
__device__ int g_cursor[NMAX];
__device__ int g_row_ptr[NMAX + 1];
__device__ int g_csr_src[EMAX];
__device__ int g_csr_code[EMAX];

#define SEL_EXT  0
#define SEL_HG   2
#define SEL_T    4
__device__ __forceinline__ float* sel_ptr(int sel, float* ext)
{
    switch (sel) {
        case SEL_HG: return g_hg;
        case SEL_T:  return g_t;
        default:     return ext;
    }
}

// ---------------- fp16 helpers ----------------
__device__ __forceinline__ unsigned pack_h2(float a, float b)
{
    __half2 p = __floats2half2_rn(a, b);
    return *reinterpret_cast<unsigned*>(&p);
}

// ---------------- smem helpers ----------------
__device__ __forceinline__ uint32_t smem_u32(const void* p)
{
    uint32_t a;
    asm("{ .reg .u64 t; cvta.to.shared.u64 t, %1; cvt.u32.u64 %0, t; }" : "=r"(a) : "l"(p));
    return a;
}
__device__ __forceinline__ void sts64(uint32_t addr, unsigned a, unsigned b)
{
    asm volatile("st.shared.v2.u32 [%0], {%1,%2};" :: "r"(addr), "r"(a), "r"(b) : "memory");
}
__device__ __forceinline__ void sts128(uint32_t addr, uint4 v)
{
    asm volatile("st.shared.v4.u32 [%0], {%1,%2,%3,%4};"
                 :: "r"(addr), "r"(v.x), "r"(v.y), "r"(v.z), "r"(v.w) : "memory");
}
__device__ __forceinline__ uint32_t lds32(uint32_t addr)
{
    uint32_t v;
    asm volatile("ld.shared.b32 %0, [%1];" : "=r"(v) : "r"(addr));
    return v;
}
__device__ __forceinline__ void mma_f16(float* c, const uint32_t* a, const uint32_t* b)
{
    asm volatile("mma.sync.aligned.m16n8k16.row.col.f32.f16.f16.f32 "
                 "{%0,%1,%2,%3}, {%4,%5,%6,%7}, {%8,%9}, {%0,%1,%2,%3};"
                 : "+f"(c[0]), "+f"(c[1]), "+f"(c[2]), "+f"(c[3])
                 : "r"(a[0]), "r"(a[1]), "r"(a[2]), "r"(a[3]), "r"(b[0]), "r"(b[1]));
}

// ================= CSR build =================
__global__ void k_zero2(int n)
{
    int i = blockIdx.x * blockDim.x + threadIdx.x;
    if (i < n) { g_deg[i] = 0; g_cursor[i] = 0; }
}
__global__ void k_count(const int* __restrict__ ei, int nE)
{
    int e = blockIdx.x * blockDim.x + threadIdx.x;
    if (e < nE) atomicAdd(&g_deg[ei[nE + e]], 1);
}
__global__ void k_scan(int n)
{
    __shared__ int sh[1024];
    int t = threadIdx.x;
    int chunk = (n + 1023) / 1024;
    int lo = t * chunk, hi = min(lo + chunk, n);
    int s = 0;
    for (int i = lo; i < hi; i++) s += g_deg[i];
    sh[t] = s;
    __syncthreads();
    for (int d = 1; d < 1024; d <<= 1) {
        int v = (t >= d) ? sh[t - d] : 0;
        __syncthreads();
        sh[t] += v;
        __syncthreads();
    }
    int run = sh[t] - s;
    for (int i = lo; i < hi; i++) { g_row_ptr[i] = run; run += g_deg[i]; }
    if (t == 1023) g_row_ptr[n] = run;
}
__global__ void k_fill(const int* __restrict__ ei, const int* __restrict__ et,
                       const int* __restrict__ ed, int nE)
{
    int e = blockIdx.x * blockDim.x + threadIdx.x;
    if (e >= nE) return;
    int c = ei[nE + e];
    int p = g_row_ptr[c] + atomicAdd(&g_cursor[c], 1);
    g_csr_src[p] = ei[e];
    g_csr_code[p] = et[e] * 3 + ed[e];
}

// ================= init: g_h = emb1[at] + emb2[ch] (fp32) =================
__global__ void k_init(const int* __restrict__ at, const int* __restrict__ ch,
                       const float* __restrict__ e1, const float* __restrict__ e2, int n)
{
    int idx = blockIdx.x * blockDim.x + threadIdx.x;
    if (idx >= n * F4) return;
    int i = idx / F4, c = idx % F4;
    float4 a = ((const float4*)e1)[(size_t)at[i] * F4 + c];
    float4 b = ((const float4*)e2)[(size_t)ch[i] * F4 + c];
    ((float4*)g_h)[idx] = make_float4(a.x + b.x, a.y + b.y, a.z + b.z, a.w + b.w);
}

// ================= per-layer: s[i] from CSR; zero col stats =================
__global__ void k_sconst(const float* __restrict__ ee1l, const float* __restrict__ ee2l, int n)
{
    int i = blockIdx.x * blockDim.x + threadIdx.x;
    if (i < n) {
        float base = ee1l[4] + ee2l[0];
        int p0 = g_row_ptr[i], p1 = g_row_ptr[i + 1];
        for (int p = p0; p < p1; p++) {
            int code = g_csr_code[p];
            base += ee1l[code / 3] + ee2l[code % 3];
        }
        g_s[i] = base;
    }
    if (i < EMBC) { g_colsum[i] = 0.f; g_colsumsq[i] = 0.f; }
}

// ================= BN scale/shift from stats =================
__global__ void k_mkscale(const float* __restrict__ gamma, const float* __restrict__ beta, int n)
{
    int i = threadIdx.x + blockIdx.x * blockDim.x;
    if (i >= EMBC) return;
    float inv_n = 1.f / (float)n;
    float mean = g_colsum[i] * inv_n;
    float var  = g_colsumsq[i] * inv_n - mean * mean;
    float sc = gamma[i] * rsqrtf(var + 1e-5f);
    g_scale[i] = sc;
    g_shift[i] = beta[i] - mean * sc;
}

// ================= W transpose -> plain fp16 =================
__global__ void k_wprep(const float* __restrict__ Wl)
{
    int idx = blockIdx.x * blockDim.x + threadIdx.x;   // over NPAD * 38 uint4s
    if (idx >= NPAD * A_U4ROW) return;
    int nrow = idx / A_U4ROW, u = idx % A_U4ROW;
    unsigned w[4];
    #pragma unroll
    for (int j = 0; j < 4; j++) {
        int k0 = u * 8 + j * 2;
        float v0 = (nrow < EMBC && k0     < EMBC) ? Wl[(size_t)k0       * EMBC + nrow] : 0.f;
        float v1 = (nrow < EMBC && k0 + 1 < EMBC) ? Wl[(size_t)(k0 + 1) * EMBC + nrow] : 0.f;
        w[j] = pack_h2(v0, v1);
    }
    ((uint4*)g_wh)[idx] = make_uint4(w[0], w[1], w[2], w[3]);
}

// ======= fused gather: aggh[i] = fp16( T(h[i]) + sum_in T(h[src]) ) =========
// mode 0: T = identity (layer 0). mode 1: T(x) = max(scale*x+shift, 0).
__global__ void k_gather2(int n, int mode)
{
    int idx = blockIdx.x * blockDim.x + threadIdx.x;
    if (idx >= n * U4W) return;
    int i = idx / U4W, c = idx % U4W;
    if (c >= F4) { ((uint2*)g_aggh)[idx] = make_uint2(0, 0); return; }
    int f = c * 4;
    float4 sc = make_float4(1.f, 1.f, 1.f, 1.f);
    float4 sh = make_float4(0.f, 0.f, 0.f, 0.f);
    if (mode) {
        sc = *(const float4*)&g_scale[f];
        sh = *(const float4*)&g_shift[f];
    }
    float4 x = *(const float4*)&g_h[(size_t)i * EMBC + f];
    float v0, v1, v2, v3;
    if (mode) {
        v0 = fmaxf(fmaf(x.x, sc.x, sh.x), 0.f); v1 = fmaxf(fmaf(x.y, sc.y, sh.y), 0.f);
        v2 = fmaxf(fmaf(x.z, sc.z, sh.z), 0.f); v3 = fmaxf(fmaf(x.w, sc.w, sh.w), 0.f);
    } else { v0 = x.x; v1 = x.y; v2 = x.z; v3 = x.w; }
    int p0 = g_row_ptr[i], p1 = g_row_ptr[i + 1];
    for (int p = p0; p < p1; p++) {
        float4 y = *(const float4*)&g_h[(size_t)g_csr_src[p] * EMBC + f];
        if (mode) {
            v0 += fmaxf(fmaf(y.x, sc.x, sh.x), 0.f); v1 += fmaxf(fmaf(y.y, sc.y, sh.y), 0.f);
            v2 += fmaxf(fmaf(y.z, sc.z, sh.z), 0.f); v3 += fmaxf(fmaf(y.w, sc.w, sh.w), 0.f);
        } else { v0 += y.x; v1 += y.y; v2 += y.z; v3 += y.w; }
    }
    uint2 o;
    o.x = pack_h2(v0, v1);
    o.y = pack_h2(v2, v3);
    ((uint2*)g_aggh)[idx] = o;
}

// ================= HMMA fp16 single-pass GEMM + fused column stats ==========
// D = Ah * Wh : 8 mma per warp-ktile.
// smem per buffer: A 128x48 = 6144 | B 64x48 = 3072 -> 9216 B.
// grid = (nb=5, mb); nb fastest so the 5 CTAs sharing an A-tile co-run (L2 reuse)
#define SBUF 9216

__global__ void __launch_bounds__(256)
k_gemm_mma(const float* __restrict__ bias, int M)
{
    __shared__ __align__(16) char smem[2 * SBUF];
    __shared__ float s_sum[64], s_sq[64];
    uint32_t sb = smem_u32(smem);
    int tid = threadIdx.x, lane = tid & 31, wid = tid >> 5;
    int wm = wid & 3, wn = wid >> 2;
    int m0 = blockIdx.y * 128, n0 = blockIdx.x * 64;
    const uint4* AGH = (const uint4*)g_aggh;   // 38 uint4 per row (fp16)
    const uint2* WGH = (const uint2*)g_wh;     // 76 uint2 per row (fp16)

    int arow = tid >> 1, apart = tid & 1;      // A copy: 128 rows x 2 x 16B
    int br0 = tid >> 2, au = tid & 3;          // B: 64 rows x 4 x 8B

    float acc[2][4][4] = {};
    uint4 pa;
    uint2 pb;

    pa = (m0 + arow < M) ? AGH[(size_t)(m0 + arow) * A_U4ROW + apart] : make_uint4(0,0,0,0);
    pb = WGH[(size_t)(n0 + br0) * W_U2ROW + au];
    {
        uint32_t base = sb;
        sts128(base + arow * 48 + apart * 16, pa);
        sts64(base + 6144 + br0 * 48 + au * 8, pb.x, pb.y);
    }
    if (tid < 64) { s_sum[tid] = 0.f; s_sq[tid] = 0.f; }
    __syncthreads();

    uint32_t aoff = (uint32_t)((wm * 32 + (lane >> 2)) * 48 + (lane & 3) * 4);
    uint32_t boff = (uint32_t)((wn * 32 + (lane >> 2)) * 48 + (lane & 3) * 4);

    for (int kt = 0; kt < NKT; kt++) {
        int b = kt & 1;
        if (kt < NKT - 1) {
            pa = (m0 + arow < M) ? AGH[(size_t)(m0 + arow) * A_U4ROW + (kt + 1) * 2 + apart]
                                 : make_uint4(0,0,0,0);
            pb = WGH[(size_t)(n0 + br0) * W_U2ROW + (kt + 1) * 4 + au];
        }
        {
            uint32_t base = sb + b * SBUF;
            uint32_t AH = base + aoff;
            uint32_t BH = base + 6144 + boff;
            uint32_t af[2][4], bh[4][2];
            #pragma unroll
            for (int mt = 0; mt < 2; mt++) {
                uint32_t r = AH + mt * 16 * 48;
                af[mt][0] = lds32(r);       af[mt][1] = lds32(r + 8 * 48);
                af[mt][2] = lds32(r + 16);  af[mt][3] = lds32(r + 8 * 48 + 16);
            }
            #pragma unroll
            for (int nt = 0; nt < 4; nt++) {
                uint32_t r = BH + nt * 8 * 48;
                bh[nt][0] = lds32(r);  bh[nt][1] = lds32(r + 16);
            }
            #pragma unroll
            for (int mt = 0; mt < 2; mt++)
                #pragma unroll
                for (int nt = 0; nt < 4; nt++)
                    mma_f16(acc[mt][nt], af[mt], bh[nt]);
        }
        if (kt < NKT - 1) {
            uint32_t base = sb + (b ^ 1) * SBUF;
            sts128(base + arow * 48 + apart * 16, pa);
            sts64(base + 6144 + br0 * 48 + au * 8, pb.x, pb.y);
        }
        __syncthreads();
    }

    // ---- epilogue: C + bias + s[row] -> g_h ; fused column stats ----
    float ls[4][2] = {}, lq[4][2] = {};
    #pragma unroll
    for (int mt = 0; mt < 2; mt++) {
        int row0 = m0 + wm * 32 + mt * 16 + (lane >> 2);
        int row1 = row0 + 8;
        float s0 = (row0 < M) ? g_s[row0] : 0.f;
        float s1 = (row1 < M) ? g_s[row1] : 0.f;
        #pragma unroll
        for (int nt = 0; nt < 4; nt++) {
            int col = n0 + wn * 32 + nt * 8 + (lane & 3) * 2;
            if (col < EMBC) {
                float b0 = bias[col], b1 = bias[col + 1];
                if (row0 < M) {
                    float v0 = acc[mt][nt][0] + b0 + s0;
                    float v1 = acc[mt][nt][1] + b1 + s0;
                    g_h[(size_t)row0 * EMBC + col]     = v0;
                    g_h[(size_t)row0 * EMBC + col + 1] = v1;
                    ls[nt][0] += v0; lq[nt][0] += v0 * v0;
                    ls[nt][1] += v1; lq[nt][1] += v1 * v1;
                }
                if (row1 < M) {
                    float v0 = acc[mt][nt][2] + b0 + s1;
                    float v1 = acc[mt][nt][3] + b1 + s1;
                    g_h[(size_t)row1 * EMBC + col]     = v0;
                    g_h[(size_t)row1 * EMBC + col + 1] = v1;
                    ls[nt][0] += v0; lq[nt][0] += v0 * v0;
                    ls[nt][1] += v1; lq[nt][1] += v1 * v1;
                }
            }
        }
    }
    #pragma unroll
    for (int nt = 0; nt < 4; nt++)
        #pragma unroll
        for (int jj = 0; jj < 2; jj++) {
            #pragma unroll
            for (int o = 4; o < 32; o <<= 1) {
                ls[nt][jj] += __shfl_xor_sync(0xffffffffu, ls[nt][jj], o);
                lq[nt][jj] += __shfl_xor_sync(0xffffffffu, lq[nt][jj], o);
            }
        }
    if (lane < 4) {
        #pragma unroll
        for (int nt = 0; nt < 4; nt++)
            #pragma unroll
            for (int jj = 0; jj < 2; jj++) {
                int ci = wn * 32 + nt * 8 + lane * 2 + jj;
                atomicAdd(&s_sum[ci], ls[nt][jj]);
                atomicAdd(&s_sq[ci],  lq[nt][jj]);
            }
    }
    __syncthreads();
    if (tid < 64) {
        int col = n0 + tid;
        if (col < EMBC) {
            atomicAdd(&g_colsum[col],   s_sum[tid]);
            atomicAdd(&g_colsumsq[col], s_sq[tid]);
        }
    }
}

// ================= mean pool with fused final BN =================
__device__ __forceinline__ int lower_bound_i(const int* a, int n, int v)
{
    int lo = 0, hi = n;
    while (lo < hi) { int m = (lo + hi) >> 1; if (a[m] < v) lo = m + 1; else hi = m; }
    return lo;
}
__global__ void k_pool(const int* __restrict__ batch, int n)
{
    int g = blockIdx.x;
    int start = lower_bound_i(batch, n, g);
    int end   = lower_bound_i(batch, n, g + 1);
    int f = threadIdx.x;
    if (f >= EMBC) return;
    float s = 0.f;
    for (int i = start; i < end; i++)
        s += g_h[(size_t)i * EMBC + f];
    float m = s / fmaxf((float)(end - start), 1.f);
    g_hg[(size_t)g * EMBC + f] = fmaf(m, g_scale[f], g_shift[f]);
}

// ================= SIMT sgemm for head =================
template<int EPI>
__global__ __launch_bounds__(256)
void k_sgemm(int a_sel, float* a_ext, const float* __restrict__ B,
             int c_sel, float* c_ext, int M, int N, int K,
             const float* __restrict__ bias)
{
    const float* A = sel_ptr(a_sel, a_ext);
    float*       C = sel_ptr(c_sel, c_ext);
    __shared__ __align__(16) float As[16][64];
    __shared__ __align__(16) float Bs[16][64];
    int tid = threadIdx.x;
    int tx = tid & 15, ty = tid >> 4;
    int m0 = blockIdx.x * 64, n0 = blockIdx.y * 64;
    int am = tid >> 2, ak4 = tid & 3;
    int bk = tid >> 4, bn4 = tid & 15;
    float acc[4][4] = {};
    for (int kt = 0; kt < K; kt += 16) {
        float4 av = make_float4(0.f, 0.f, 0.f, 0.f);
        int arow = m0 + am, acol = kt + ak4 * 4;
        if (arow < M && acol + 4 <= K)
            av = *(const float4*)(A + (size_t)arow * K + acol);
        As[ak4 * 4 + 0][am] = av.x;
        As[ak4 * 4 + 1][am] = av.y;
        As[ak4 * 4 + 2][am] = av.z;
        As[ak4 * 4 + 3][am] = av.w;
        float4 bv = make_float4(0.f, 0.f, 0.f, 0.f);
        int brow = kt + bk, bcol = n0 + bn4 * 4;
        if (brow < K && bcol + 4 <= N)
            bv = *(const float4*)(B + (size_t)brow * N + bcol);
        *(float4*)&Bs[bk][bn4 * 4] = bv;
        __syncthreads();
        #pragma unroll
        for (int k = 0; k < 16; k++) {
            float4 a4 = *(const float4*)&As[k][ty * 4];
            float4 b4 = *(const float4*)&Bs[k][tx * 4];
            float ar[4] = {a4.x, a4.y, a4.z, a4.w};
            float br[4] = {b4.x, b4.y, b4.z, b4.w};
            #pragma unroll
            for (int i = 0; i < 4; i++)
                #pragma unroll
                for (int j = 0; j < 4; j++)
                    acc[i][j] += ar[i] * br[j];
        }
        __syncthreads();
    }
    float bb[4];
    #pragma unroll
    for (int j = 0; j < 4; j++) {
        int col = n0 + tx * 4 + j;
        bb[j] = (col < N) ? bias[col] : 0.f;
    }
    #pragma unroll
    for (int i = 0; i < 4; i++) {
        int row = m0 + ty * 4 + i;
        if (row >= M) continue;
        #pragma unroll
        for (int j = 0; j < 4; j++) {
            int col = n0 + tx * 4 + j;
            if (col >= N) continue;
            float v = acc[i][j] + bb[j];
            if (EPI == 1)
                v = (v > 0.f) ? v + log1pf(expf(-v)) : log1pf(expf(v));
            C[(size_t)row * N + col] = v;
        }
    }
}

__global__ void k_pred(const float* __restrict__ W2, const float* __restrict__ b2,
                       float* __restrict__ out)
{
    int g = blockIdx.x;
    int w = threadIdx.x >> 5;
    int lane = threadIdx.x & 31;
    float s = 0.f;
    #pragma unroll
    for (int q = 0; q < 4; q++) {
        int i = lane * 4 + q;
        s += g_t[(size_t)g * 128 + i] * W2[i * 2 + w];
    }
    #pragma unroll
    for (int o = 16; o > 0; o >>= 1) s += __shfl_xor_sync(0xffffffffu, s, o);
    if (lane == 0) out[g * 2 + w] = s + b2[w];
}

// ======================================================================
extern "C" void kernel_launch(void* const* d_in, const int* in_sizes, int n_in,
                              void* d_out, int out_size)
{
    const int*   atom_type = (const int*)d_in[0];
    const int*   chirality = (const int*)d_in[1];
    const int*   edge_index= (const int*)d_in[2];
    const int*   edge_type = (const int*)d_in[3];
    const int*   edge_dir  = (const int*)d_in[4];
    const int*   batch     = (const int*)d_in[5];
    const float* atom_emb1 = (const float*)d_in[6];
    const float* atom_emb2 = (const float*)d_in[7];
    const float* W         = (const float*)d_in[8];
    const float* b         = (const float*)d_in[9];
    const float* ee1       = (const float*)d_in[10];
    const float* ee2       = (const float*)d_in[11];
    const float* bn_gamma  = (const float*)d_in[12];
    const float* bn_beta   = (const float*)d_in[13];
    const float* feat_W    = (const float*)d_in[14];
    const float* feat_b    = (const float*)d_in[15];
    const float* head_W1   = (const float*)d_in[16];
    const float* head_b1   = (const float*)d_in[17];
    const float* head_W2   = (const float*)d_in[18];
    const float* head_b2   = (const float*)d_in[19];

    int N  = in_sizes[0];
    int E  = in_sizes[3];
    int NG = out_size / (256 + 2);

    float* out_f = (float*)d_out;
    float* hf    = out_f;
    float* pred  = out_f + (size_t)NG * 256;

    // CSR build
    k_zero2<<<(N + 255) / 256, 256>>>(N);
    k_count<<<(E + 255) / 256, 256>>>(edge_index, E);
    k_scan<<<1, 1024>>>(N);
    k_fill<<<(E + 255) / 256, 256>>>(edge_index, edge_type, edge_dir, E);

    // embedding init (fp32 h)
    k_init<<<(N * F4 + 255) / 256, 256>>>(atom_type, chirality, atom_emb1, atom_emb2, N);

    dim3 ggrid(NPAD / 64, (N + 127) / 128);   // nb fastest -> A-tile L2 reuse
    for (int l = 0; l < NLAYER; l++) {
        const float* Wl   = W  + (size_t)l * EMBC * EMBC;
        const float* bl   = b  + (size_t)l * EMBC;
        const float* ee1l = ee1 + l * 5;
        const float* ee2l = ee2 + l * 3;

        if (l > 0)
            k_mkscale<<<2, 160>>>(bn_gamma + (l - 1) * EMBC, bn_beta + (l - 1) * EMBC, N);
        k_sconst<<<(N + 255) / 256, 256>>>(ee1l, ee2l, N);
        k_wprep<<<(NPAD * A_U4ROW + 255) / 256, 256>>>(Wl);
        k_gather2<<<(N * U4W + 255) / 256, 256>>>(N, l > 0 ? 1 : 0);
        k_gemm_mma<<<ggrid, 256>>>(bl, N);
    }

    // final BN folded into pooling
    k_mkscale<<<2, 160>>>(bn_gamma + (NLAYER - 1) * EMBC, bn_beta + (NLAYER - 1) * EMBC, N);

    k_pool<<<NG, 320>>>(batch, N);
    {
        dim3 grid((NG + 63) / 64, (256 + 63) / 64);
        k_sgemm<0><<<grid, 256>>>(SEL_HG, nullptr, feat_W, SEL_EXT, hf,
                                  NG, 256, EMBC, feat_b);
    }
    {
        dim3 grid((NG + 63) / 64, (128 + 63) / 64);
        k_sgemm<1><<<grid, 256>>>(SEL_EXT, hf, head_W1, SEL_T, nullptr,
                                  NG, 128, 256, head_b1);
    }
    k_pred<<<NG, 64>>>(head_W2, head_b2, pred);
}

// round 13
// speedup vs baseline: 1.5866x; 1.1765x over previous
#include <cuda_runtime.h>
#include <cuda_bf16.h>
#include <cuda_fp16.h>
#include <math.h>
#include <stdint.h>

#define NMAX    100000
#define EMBC    300
#define F4      75
#define KP      304         // padded K: 19 k16 tiles
#define U4W     76          // gather chunk count (75 data + 1 pad)
#define A_U4ROW 38          // uint4s per fp16 A row: 304 halves / 8
#define W_U2ROW 76          // uint2s per fp16 W row: 304 halves / 4
#define NPAD    320         // padded N (output cols)
#define NKT     19
#define NGMAX   4096
#define NLAYER  5
#define EMAX    200000

// ---------------- device scratch ----------------
__device__ __align__(16) unsigned short g_aggh[(size_t)NMAX * KP];  // fp16 gathered A
__device__ __align__(16) unsigned short g_hh [(size_t)NMAX * EMBC]; // fp16 activations (pre-BN)
__device__ __align__(16) unsigned short g_wh[NPAD * KP];            // fp16 W^T
__device__ float g_s[NMAX];
__device__ float g_colsum[EMBC];
__device__ float g_colsumsq[EMBC];
__device__ float g_scale[EMBC];
__device__ float g_shift[EMBC];
__device__ __align__(16) float g_hg[(size_t)NGMAX * EMBC];
__device__ __align__(16) float g_t [(size_t)NGMAX * 128];
__device__ int g_deg[NMAX];
__device__ int g_cursor[NMAX];
__device__ int g_row_ptr[NMAX + 1];
__device__ int g_csr_src[EMAX];
__device__ int g_csr_code[EMAX];

#define SEL_EXT  0
#define SEL_HG   2
#define SEL_T    4
__device__ __forceinline__ float* sel_ptr(int sel, float* ext)
{
    switch (sel) {
        case SEL_HG: return g_hg;
        case SEL_T:  return g_t;
        default:     return ext;
    }
}

// ---------------- fp16 helpers ----------------
__device__ __forceinline__ unsigned pack_h2(float a, float b)
{
    __half2 p = __floats2half2_rn(a, b);
    return *reinterpret_cast<unsigned*>(&p);
}
__device__ __forceinline__ float2 unpack_h2(unsigned u)
{
    __half2 p = *reinterpret_cast<__half2*>(&u);
    return __half22float2(p);
}

// ---------------- smem helpers ----------------
__device__ __forceinline__ uint32_t smem_u32(const void* p)
{
    uint32_t a;
    asm("{ .reg .u64 t; cvta.to.shared.u64 t, %1; cvt.u32.u64 %0, t; }" : "=r"(a) : "l"(p));
    return a;
}
__device__ __forceinline__ void sts64(uint32_t addr, unsigned a, unsigned b)
{
    asm volatile("st.shared.v2.u32 [%0], {%1,%2};" :: "r"(addr), "r"(a), "r"(b) : "memory");
}
__device__ __forceinline__ void sts128(uint32_t addr, uint4 v)
{
    asm volatile("st.shared.v4.u32 [%0], {%1,%2,%3,%4};"
                 :: "r"(addr), "r"(v.x), "r"(v.y), "r"(v.z), "r"(v.w) : "memory");
}
__device__ __forceinline__ uint32_t lds32(uint32_t addr)
{
    uint32_t v;
    asm volatile("ld.shared.b32 %0, [%1];" : "=r"(v) : "r"(addr));
    return v;
}
__device__ __forceinline__ void mma_f16(float* c, const uint32_t* a, const uint32_t* b)
{
    asm volatile("mma.sync.aligned.m16n8k16.row.col.f32.f16.f16.f32 "
                 "{%0,%1,%2,%3}, {%4,%5,%6,%7}, {%8,%9}, {%0,%1,%2,%3};"
                 : "+f"(c[0]), "+f"(c[1]), "+f"(c[2]), "+f"(c[3])
                 : "r"(a[0]), "r"(a[1]), "r"(a[2]), "r"(a[3]), "r"(b[0]), "r"(b[1]));
}

// ================= CSR build =================
__global__ void k_zero2(int n)
{
    int i = blockIdx.x * blockDim.x + threadIdx.x;
    if (i < n) { g_deg[i] = 0; g_cursor[i] = 0; }
}
__global__ void k_count(const int* __restrict__ ei, int nE)
{
    int e = blockIdx.x * blockDim.x + threadIdx.x;
    if (e < nE) atomicAdd(&g_deg[ei[nE + e]], 1);
}
__global__ void k_scan(int n)
{
    __shared__ int sh[1024];
    int t = threadIdx.x;
    int chunk = (n + 1023) / 1024;
    int lo = t * chunk, hi = min(lo + chunk, n);
    int s = 0;
    for (int i = lo; i < hi; i++) s += g_deg[i];
    sh[t] = s;
    __syncthreads();
    for (int d = 1; d < 1024; d <<= 1) {
        int v = (t >= d) ? sh[t - d] : 0;
        __syncthreads();
        sh[t] += v;
        __syncthreads();
    }
    int run = sh[t] - s;
    for (int i = lo; i < hi; i++) { g_row_ptr[i] = run; run += g_deg[i]; }
    if (t == 1023) g_row_ptr[n] = run;
}
__global__ void k_fill(const int* __restrict__ ei, const int* __restrict__ et,
                       const int* __restrict__ ed, int nE)
{
    int e = blockIdx.x * blockDim.x + threadIdx.x;
    if (e >= nE) return;
    int c = ei[nE + e];
    int p = g_row_ptr[c] + atomicAdd(&g_cursor[c], 1);
    g_csr_src[p] = ei[e];
    g_csr_code[p] = et[e] * 3 + ed[e];
}

// ================= init: g_hh = fp16(emb1[at] + emb2[ch]) =================
__global__ void k_init(const int* __restrict__ at, const int* __restrict__ ch,
                       const float* __restrict__ e1, const float* __restrict__ e2, int n)
{
    int idx = blockIdx.x * blockDim.x + threadIdx.x;
    if (idx >= n * F4) return;
    int i = idx / F4, c = idx % F4;
    float4 a = ((const float4*)e1)[(size_t)at[i] * F4 + c];
    float4 b = ((const float4*)e2)[(size_t)ch[i] * F4 + c];
    uint2 o;
    o.x = pack_h2(a.x + b.x, a.y + b.y);
    o.y = pack_h2(a.z + b.z, a.w + b.w);
    ((uint2*)g_hh)[idx] = o;
}

// ================= per-layer: s[i] from CSR; zero col stats =================
__global__ void k_sconst(const float* __restrict__ ee1l, const float* __restrict__ ee2l, int n)
{
    int i = blockIdx.x * blockDim.x + threadIdx.x;
    if (i < n) {
        float base = ee1l[4] + ee2l[0];
        int p0 = g_row_ptr[i], p1 = g_row_ptr[i + 1];
        for (int p = p0; p < p1; p++) {
            int code = g_csr_code[p];
            base += ee1l[code / 3] + ee2l[code % 3];
        }
        g_s[i] = base;
    }
    if (i < EMBC) { g_colsum[i] = 0.f; g_colsumsq[i] = 0.f; }
}

// ================= BN scale/shift from stats =================
__global__ void k_mkscale(const float* __restrict__ gamma, const float* __restrict__ beta, int n)
{
    int i = threadIdx.x + blockIdx.x * blockDim.x;
    if (i >= EMBC) return;
    float inv_n = 1.f / (float)n;
    float mean = g_colsum[i] * inv_n;
    float var  = g_colsumsq[i] * inv_n - mean * mean;
    float sc = gamma[i] * rsqrtf(var + 1e-5f);
    g_scale[i] = sc;
    g_shift[i] = beta[i] - mean * sc;
}

// ================= W transpose -> plain fp16 =================
__global__ void k_wprep(const float* __restrict__ Wl)
{
    int idx = blockIdx.x * blockDim.x + threadIdx.x;   // over NPAD * 38 uint4s
    if (idx >= NPAD * A_U4ROW) return;
    int nrow = idx / A_U4ROW, u = idx % A_U4ROW;
    unsigned w[4];
    #pragma unroll
    for (int j = 0; j < 4; j++) {
        int k0 = u * 8 + j * 2;
        float v0 = (nrow < EMBC && k0     < EMBC) ? Wl[(size_t)k0       * EMBC + nrow] : 0.f;
        float v1 = (nrow < EMBC && k0 + 1 < EMBC) ? Wl[(size_t)(k0 + 1) * EMBC + nrow] : 0.f;
        w[j] = pack_h2(v0, v1);
    }
    ((uint4*)g_wh)[idx] = make_uint4(w[0], w[1], w[2], w[3]);
}

// ======= fused gather: aggh[i] = fp16( T(hh[i]) + sum_in T(hh[src]) ) =======
// mode 0: T = identity (layer 0). mode 1: T(x) = max(scale*x+shift, 0).
__global__ void k_gather2(int n, int mode)
{
    int idx = blockIdx.x * blockDim.x + threadIdx.x;
    if (idx >= n * U4W) return;
    int i = idx / U4W, c = idx % U4W;
    if (c >= F4) { ((uint2*)g_aggh)[idx] = make_uint2(0, 0); return; }
    int f = c * 4;
    float4 sc = make_float4(1.f, 1.f, 1.f, 1.f);
    float4 sh = make_float4(0.f, 0.f, 0.f, 0.f);
    if (mode) {
        sc = *(const float4*)&g_scale[f];
        sh = *(const float4*)&g_shift[f];
    }
    const uint2* HH = (const uint2*)g_hh;
    uint2 hx = HH[(size_t)i * F4 + c];
    float2 xa = unpack_h2(hx.x), xb = unpack_h2(hx.y);
    float v0, v1, v2, v3;
    if (mode) {
        v0 = fmaxf(fmaf(xa.x, sc.x, sh.x), 0.f); v1 = fmaxf(fmaf(xa.y, sc.y, sh.y), 0.f);
        v2 = fmaxf(fmaf(xb.x, sc.z, sh.z), 0.f); v3 = fmaxf(fmaf(xb.y, sc.w, sh.w), 0.f);
    } else { v0 = xa.x; v1 = xa.y; v2 = xb.x; v3 = xb.y; }
    int p0 = g_row_ptr[i], p1 = g_row_ptr[i + 1];
    for (int p = p0; p < p1; p++) {
        uint2 hy = HH[(size_t)g_csr_src[p] * F4 + c];
        float2 ya = unpack_h2(hy.x), yb = unpack_h2(hy.y);
        if (mode) {
            v0 += fmaxf(fmaf(ya.x, sc.x, sh.x), 0.f); v1 += fmaxf(fmaf(ya.y, sc.y, sh.y), 0.f);
            v2 += fmaxf(fmaf(yb.x, sc.z, sh.z), 0.f); v3 += fmaxf(fmaf(yb.y, sc.w, sh.w), 0.f);
        } else { v0 += ya.x; v1 += ya.y; v2 += yb.x; v3 += yb.y; }
    }
    uint2 o;
    o.x = pack_h2(v0, v1);
    o.y = pack_h2(v2, v3);
    ((uint2*)g_aggh)[idx] = o;
}

// ================= HMMA fp16 single-pass GEMM + fused column stats ==========
// D = Ah * Wh : 8 mma per warp-ktile. Epilogue writes fp16 h + fp32 stats.
// smem per buffer: A 128x48 = 6144 | B 64x48 = 3072 -> 9216 B.
#define SBUF 9216

__global__ void __launch_bounds__(256)
k_gemm_mma(const float* __restrict__ bias, int M)
{
    __shared__ __align__(16) char smem[2 * SBUF];
    __shared__ float s_sum[64], s_sq[64];
    uint32_t sb = smem_u32(smem);
    int tid = threadIdx.x, lane = tid & 31, wid = tid >> 5;
    int wm = wid & 3, wn = wid >> 2;
    int m0 = blockIdx.y * 128, n0 = blockIdx.x * 64;
    const uint4* AGH = (const uint4*)g_aggh;   // 38 uint4 per row (fp16)
    const uint2* WGH = (const uint2*)g_wh;     // 76 uint2 per row (fp16)

    int arow = tid >> 1, apart = tid & 1;      // A copy: 128 rows x 2 x 16B
    int br0 = tid >> 2, au = tid & 3;          // B: 64 rows x 4 x 8B

    float acc[2][4][4] = {};
    uint4 pa;
    uint2 pb;

    pa = (m0 + arow < M) ? AGH[(size_t)(m0 + arow) * A_U4ROW + apart] : make_uint4(0,0,0,0);
    pb = WGH[(size_t)(n0 + br0) * W_U2ROW + au];
    {
        uint32_t base = sb;
        sts128(base + arow * 48 + apart * 16, pa);
        sts64(base + 6144 + br0 * 48 + au * 8, pb.x, pb.y);
    }
    if (tid < 64) { s_sum[tid] = 0.f; s_sq[tid] = 0.f; }
    __syncthreads();

    uint32_t aoff = (uint32_t)((wm * 32 + (lane >> 2)) * 48 + (lane & 3) * 4);
    uint32_t boff = (uint32_t)((wn * 32 + (lane >> 2)) * 48 + (lane & 3) * 4);

    for (int kt = 0; kt < NKT; kt++) {
        int b = kt & 1;
        if (kt < NKT - 1) {
            pa = (m0 + arow < M) ? AGH[(size_t)(m0 + arow) * A_U4ROW + (kt + 1) * 2 + apart]
                                 : make_uint4(0,0,0,0);
            pb = WGH[(size_t)(n0 + br0) * W_U2ROW + (kt + 1) * 4 + au];
        }
        {
            uint32_t base = sb + b * SBUF;
            uint32_t AH = base + aoff;
            uint32_t BH = base + 6144 + boff;
            uint32_t af[2][4], bh[4][2];
            #pragma unroll
            for (int mt = 0; mt < 2; mt++) {
                uint32_t r = AH + mt * 16 * 48;
                af[mt][0] = lds32(r);       af[mt][1] = lds32(r + 8 * 48);
                af[mt][2] = lds32(r + 16);  af[mt][3] = lds32(r + 8 * 48 + 16);
            }
            #pragma unroll
            for (int nt = 0; nt < 4; nt++) {
                uint32_t r = BH + nt * 8 * 48;
                bh[nt][0] = lds32(r);  bh[nt][1] = lds32(r + 16);
            }
            #pragma unroll
            for (int mt = 0; mt < 2; mt++)
                #pragma unroll
                for (int nt = 0; nt < 4; nt++)
                    mma_f16(acc[mt][nt], af[mt], bh[nt]);
        }
        if (kt < NKT - 1) {
            uint32_t base = sb + (b ^ 1) * SBUF;
            sts128(base + arow * 48 + apart * 16, pa);
            sts64(base + 6144 + br0 * 48 + au * 8, pb.x, pb.y);
        }
        __syncthreads();
    }

    // ---- epilogue: C + bias + s[row] -> g_hh (fp16 pair) ; fused stats -----
    unsigned* HO = (unsigned*)g_hh;
    float ls[4][2] = {}, lq[4][2] = {};
    #pragma unroll
    for (int mt = 0; mt < 2; mt++) {
        int row0 = m0 + wm * 32 + mt * 16 + (lane >> 2);
        int row1 = row0 + 8;
        float s0 = (row0 < M) ? g_s[row0] : 0.f;
        float s1 = (row1 < M) ? g_s[row1] : 0.f;
        #pragma unroll
        for (int nt = 0; nt < 4; nt++) {
            int col = n0 + wn * 32 + nt * 8 + (lane & 3) * 2;
            if (col < EMBC) {
                float b0 = bias[col], b1 = bias[col + 1];
                if (row0 < M) {
                    float v0 = acc[mt][nt][0] + b0 + s0;
                    float v1 = acc[mt][nt][1] + b1 + s0;
                    HO[(size_t)row0 * (EMBC / 2) + (col >> 1)] = pack_h2(v0, v1);
                    ls[nt][0] += v0; lq[nt][0] += v0 * v0;
                    ls[nt][1] += v1; lq[nt][1] += v1 * v1;
                }
                if (row1 < M) {
                    float v0 = acc[mt][nt][2] + b0 + s1;
                    float v1 = acc[mt][nt][3] + b1 + s1;
                    HO[(size_t)row1 * (EMBC / 2) + (col >> 1)] = pack_h2(v0, v1);
                    ls[nt][0] += v0; lq[nt][0] += v0 * v0;
                    ls[nt][1] += v1; lq[nt][1] += v1 * v1;
                }
            }
        }
    }
    #pragma unroll
    for (int nt = 0; nt < 4; nt++)
        #pragma unroll
        for (int jj = 0; jj < 2; jj++) {
            #pragma unroll
            for (int o = 4; o < 32; o <<= 1) {
                ls[nt][jj] += __shfl_xor_sync(0xffffffffu, ls[nt][jj], o);
                lq[nt][jj] += __shfl_xor_sync(0xffffffffu, lq[nt][jj], o);
            }
        }
    if (lane < 4) {
        #pragma unroll
        for (int nt = 0; nt < 4; nt++)
            #pragma unroll
            for (int jj = 0; jj < 2; jj++) {
                int ci = wn * 32 + nt * 8 + lane * 2 + jj;
                atomicAdd(&s_sum[ci], ls[nt][jj]);
                atomicAdd(&s_sq[ci],  lq[nt][jj]);
            }
    }
    __syncthreads();
    if (tid < 64) {
        int col = n0 + tid;
        if (col < EMBC) {
            atomicAdd(&g_colsum[col],   s_sum[tid]);
            atomicAdd(&g_colsumsq[col], s_sq[tid]);
        }
    }
}

// ================= mean pool with fused final BN (fp16 h) =================
__device__ __forceinline__ int lower_bound_i(const int* a, int n, int v)
{
    int lo = 0, hi = n;
    while (lo < hi) { int m = (lo + hi) >> 1; if (a[m] < v) lo = m + 1; else hi = m; }
    return lo;
}
__global__ void k_pool(const int* __restrict__ batch, int n)
{
    int g = blockIdx.x;
    int start = lower_bound_i(batch, n, g);
    int end   = lower_bound_i(batch, n, g + 1);
    int t = threadIdx.x;            // 150 threads, each handles 2 cols
    if (t >= EMBC / 2) return;
    const unsigned* HH = (const unsigned*)g_hh;
    float s0 = 0.f, s1 = 0.f;
    for (int i = start; i < end; i++) {
        float2 v = unpack_h2(HH[(size_t)i * (EMBC / 2) + t]);
        s0 += v.x; s1 += v.y;
    }
    float inv = 1.f / fmaxf((float)(end - start), 1.f);
    int f = t * 2;
    g_hg[(size_t)g * EMBC + f]     = fmaf(s0 * inv, g_scale[f],     g_shift[f]);
    g_hg[(size_t)g * EMBC + f + 1] = fmaf(s1 * inv, g_scale[f + 1], g_shift[f + 1]);
}

// ================= SIMT sgemm for head =================
template<int EPI>
__global__ __launch_bounds__(256)
void k_sgemm(int a_sel, float* a_ext, const float* __restrict__ B,
             int c_sel, float* c_ext, int M, int N, int K,
             const float* __restrict__ bias)
{
    const float* A = sel_ptr(a_sel, a_ext);
    float*       C = sel_ptr(c_sel, c_ext);
    __shared__ __align__(16) float As[16][64];
    __shared__ __align__(16) float Bs[16][64];
    int tid = threadIdx.x;
    int tx = tid & 15, ty = tid >> 4;
    int m0 = blockIdx.x * 64, n0 = blockIdx.y * 64;
    int am = tid >> 2, ak4 = tid & 3;
    int bk = tid >> 4, bn4 = tid & 15;
    float acc[4][4] = {};
    for (int kt = 0; kt < K; kt += 16) {
        float4 av = make_float4(0.f, 0.f, 0.f, 0.f);
        int arow = m0 + am, acol = kt + ak4 * 4;
        if (arow < M && acol + 4 <= K)
            av = *(const float4*)(A + (size_t)arow * K + acol);
        As[ak4 * 4 + 0][am] = av.x;
        As[ak4 * 4 + 1][am] = av.y;
        As[ak4 * 4 + 2][am] = av.z;
        As[ak4 * 4 + 3][am] = av.w;
        float4 bv = make_float4(0.f, 0.f, 0.f, 0.f);
        int brow = kt + bk, bcol = n0 + bn4 * 4;
        if (brow < K && bcol + 4 <= N)
            bv = *(const float4*)(B + (size_t)brow * N + bcol);
        *(float4*)&Bs[bk][bn4 * 4] = bv;
        __syncthreads();
        #pragma unroll
        for (int k = 0; k < 16; k++) {
            float4 a4 = *(const float4*)&As[k][ty * 4];
            float4 b4 = *(const float4*)&Bs[k][tx * 4];
            float ar[4] = {a4.x, a4.y, a4.z, a4.w};
            float br[4] = {b4.x, b4.y, b4.z, b4.w};
            #pragma unroll
            for (int i = 0; i < 4; i++)
                #pragma unroll
                for (int j = 0; j < 4; j++)
                    acc[i][j] += ar[i] * br[j];
        }
        __syncthreads();
    }
    float bb[4];
    #pragma unroll
    for (int j = 0; j < 4; j++) {
        int col = n0 + tx * 4 + j;
        bb[j] = (col < N) ? bias[col] : 0.f;
    }
    #pragma unroll
    for (int i = 0; i < 4; i++) {
        int row = m0 + ty * 4 + i;
        if (row >= M) continue;
        #pragma unroll
        for (int j = 0; j < 4; j++) {
            int col = n0 + tx * 4 + j;
            if (col >= N) continue;
            float v = acc[i][j] + bb[j];
            if (EPI == 1)
                v = (v > 0.f) ? v + log1pf(expf(-v)) : log1pf(expf(v));
            C[(size_t)row * N + col] = v;
        }
    }
}

__global__ void k_pred(const float* __restrict__ W2, const float* __restrict__ b2,
                       float* __restrict__ out)
{
    int g = blockIdx.x;
    int w = threadIdx.x >> 5;
    int lane = threadIdx.x & 31;
    float s = 0.f;
    #pragma unroll
    for (int q = 0; q < 4; q++) {
        int i = lane * 4 + q;
        s += g_t[(size_t)g * 128 + i] * W2[i * 2 + w];
    }
    #pragma unroll
    for (int o = 16; o > 0; o >>= 1) s += __shfl_xor_sync(0xffffffffu, s, o);
    if (lane == 0) out[g * 2 + w] = s + b2[w];
}

// ======================================================================
extern "C" void kernel_launch(void* const* d_in, const int* in_sizes, int n_in,
                              void* d_out, int out_size)
{
    const int*   atom_type = (const int*)d_in[0];
    const int*   chirality = (const int*)d_in[1];
    const int*   edge_index= (const int*)d_in[2];
    const int*   edge_type = (const int*)d_in[3];
    const int*   edge_dir  = (const int*)d_in[4];
    const int*   batch     = (const int*)d_in[5];
    const float* atom_emb1 = (const float*)d_in[6];
    const float* atom_emb2 = (const float*)d_in[7];
    const float* W         = (const float*)d_in[8];
    const float* b         = (const float*)d_in[9];
    const float* ee1       = (const float*)d_in[10];
    const float* ee2       = (const float*)d_in[11];
    const float* bn_gamma  = (const float*)d_in[12];
    const float* bn_beta   = (const float*)d_in[13];
    const float* feat_W    = (const float*)d_in[14];
    const float* feat_b    = (const float*)d_in[15];
    const float* head_W1   = (const float*)d_in[16];
    const float* head_b1   = (const float*)d_in[17];
    const float* head_W2   = (const float*)d_in[18];
    const float* head_b2   = (const float*)d_in[19];

    int N  = in_sizes[0];
    int E  = in_sizes[3];
    int NG = out_size / (256 + 2);

    float* out_f = (float*)d_out;
    float* hf    = out_f;
    float* pred  = out_f + (size_t)NG * 256;

    // CSR build
    k_zero2<<<(N + 255) / 256, 256>>>(N);
    k_count<<<(E + 255) / 256, 256>>>(edge_index, E);
    k_scan<<<1, 1024>>>(N);
    k_fill<<<(E + 255) / 256, 256>>>(edge_index, edge_type, edge_dir, E);

    // embedding init (fp16 h)
    k_init<<<(N * F4 + 255) / 256, 256>>>(atom_type, chirality, atom_emb1, atom_emb2, N);

    dim3 ggrid(NPAD / 64, (N + 127) / 128);   // nb fastest -> A-tile L2 reuse
    for (int l = 0; l < NLAYER; l++) {
        const float* Wl   = W  + (size_t)l * EMBC * EMBC;
        const float* bl   = b  + (size_t)l * EMBC;
        const float* ee1l = ee1 + l * 5;
        const float* ee2l = ee2 + l * 3;

        if (l > 0)
            k_mkscale<<<2, 160>>>(bn_gamma + (l - 1) * EMBC, bn_beta + (l - 1) * EMBC, N);
        k_sconst<<<(N + 255) / 256, 256>>>(ee1l, ee2l, N);
        k_wprep<<<(NPAD * A_U4ROW + 255) / 256, 256>>>(Wl);
        k_gather2<<<(N * U4W + 255) / 256, 256>>>(N, l > 0 ? 1 : 0);
        k_gemm_mma<<<ggrid, 256>>>(bl, N);
    }

    // final BN folded into pooling
    k_mkscale<<<2, 160>>>(bn_gamma + (NLAYER - 1) * EMBC, bn_beta + (NLAYER - 1) * EMBC, N);

    k_pool<<<NG, 160>>>(batch, N);
    {
        dim3 grid((NG + 63) / 64, (256 + 63) / 64);
        k_sgemm<0><<<grid, 256>>>(SEL_HG, nullptr, feat_W, SEL_EXT, hf,
                                  NG, 256, EMBC, feat_b);
    }
    {
        dim3 grid((NG + 63) / 64, (128 + 63) / 64);
        k_sgemm<1><<<grid, 256>>>(SEL_EXT, hf, head_W1, SEL_T, nullptr,
                                  NG, 128, 256, head_b1);
    }
    k_pred<<<NG, 64>>>(head_W2, head_b2, pred);
}

// round 14
// speedup vs baseline: 1.6472x; 1.0382x over previous
#include <cuda_runtime.h>
#include <cuda_bf16.h>
#include <cuda_fp16.h>
#include <math.h>
#include <stdint.h>

#define NMAX    100000
#define EMBC    300
#define F4      75
#define KP      320         // padded K: 10 k32 tiles
#define GCH     80          // gather chunks per row (4 halves each): 320/4
#define A_U4ROW 40          // uint4s per fp16 A row: 320/8
#define W_U4ROW 40          // uint4s per fp16 W row: 320/8
#define NPAD    320         // padded N (output cols)
#define NKT     10          // k32 tiles
#define NGMAX   4096
#define NLAYER  5
#define EMAX    200000

// ---------------- device scratch ----------------
__device__ __align__(16) unsigned short g_aggh[(size_t)NMAX * KP];  // fp16 gathered A
__device__ __align__(16) unsigned short g_hh [(size_t)NMAX * EMBC]; // fp16 activations (pre-BN)
__device__ __align__(16) unsigned short g_wh[NPAD * KP];            // fp16 W^T
__device__ float g_s[NMAX];
__device__ float g_colsum[EMBC];
__device__ float g_colsumsq[EMBC];
__device__ float g_scale[EMBC];
__device__ float g_shift[EMBC];
__device__ __align__(16) float g_hg[(size_t)NGMAX * EMBC];
__device__ __align__(16) float g_t [(size_t)NGMAX * 128];
__device__ int g_deg[NMAX];
__device__ int g_cursor[NMAX];
__device__ int g_row_ptr[NMAX + 1];
__device__ int g_csr_src[EMAX];
__device__ int g_csr_code[EMAX];

#define SEL_EXT  0
#define SEL_HG   2
#define SEL_T    4
__device__ __forceinline__ float* sel_ptr(int sel, float* ext)
{
    switch (sel) {
        case SEL_HG: return g_hg;
        case SEL_T:  return g_t;
        default:     return ext;
    }
}

// ---------------- fp16 helpers ----------------
__device__ __forceinline__ unsigned pack_h2(float a, float b)
{
    __half2 p = __floats2half2_rn(a, b);
    return *reinterpret_cast<unsigned*>(&p);
}
__device__ __forceinline__ float2 unpack_h2(unsigned u)
{
    __half2 p = *reinterpret_cast<__half2*>(&u);
    return __half22float2(p);
}

// ---------------- smem helpers ----------------
__device__ __forceinline__ uint32_t smem_u32(const void* p)
{
    uint32_t a;
    asm("{ .reg .u64 t; cvta.to.shared.u64 t, %1; cvt.u32.u64 %0, t; }" : "=r"(a) : "l"(p));
    return a;
}
__device__ __forceinline__ void sts128(uint32_t addr, uint4 v)
{
    asm volatile("st.shared.v4.u32 [%0], {%1,%2,%3,%4};"
                 :: "r"(addr), "r"(v.x), "r"(v.y), "r"(v.z), "r"(v.w) : "memory");
}
__device__ __forceinline__ uint32_t lds32(uint32_t addr)
{
    uint32_t v;
    asm volatile("ld.shared.b32 %0, [%1];" : "=r"(v) : "r"(addr));
    return v;
}
__device__ __forceinline__ void mma_f16(float* c, const uint32_t* a, const uint32_t* b)
{
    asm volatile("mma.sync.aligned.m16n8k16.row.col.f32.f16.f16.f32 "
                 "{%0,%1,%2,%3}, {%4,%5,%6,%7}, {%8,%9}, {%0,%1,%2,%3};"
                 : "+f"(c[0]), "+f"(c[1]), "+f"(c[2]), "+f"(c[3])
                 : "r"(a[0]), "r"(a[1]), "r"(a[2]), "r"(a[3]), "r"(b[0]), "r"(b[1]));
}

// ================= CSR build =================
__global__ void k_zero2(int n)
{
    int i = blockIdx.x * blockDim.x + threadIdx.x;
    if (i < n) { g_deg[i] = 0; g_cursor[i] = 0; }
}
__global__ void k_count(const int* __restrict__ ei, int nE)
{
    int e = blockIdx.x * blockDim.x + threadIdx.x;
    if (e < nE) atomicAdd(&g_deg[ei[nE + e]], 1);
}
__global__ void k_scan(int n)
{
    __shared__ int sh[1024];
    int t = threadIdx.x;
    int chunk = (n + 1023) / 1024;
    int lo = t * chunk, hi = min(lo + chunk, n);
    int s = 0;
    for (int i = lo; i < hi; i++) s += g_deg[i];
    sh[t] = s;
    __syncthreads();
    for (int d = 1; d < 1024; d <<= 1) {
        int v = (t >= d) ? sh[t - d] : 0;
        __syncthreads();
        sh[t] += v;
        __syncthreads();
    }
    int run = sh[t] - s;
    for (int i = lo; i < hi; i++) { g_row_ptr[i] = run; run += g_deg[i]; }
    if (t == 1023) g_row_ptr[n] = run;
}
__global__ void k_fill(const int* __restrict__ ei, const int* __restrict__ et,
                       const int* __restrict__ ed, int nE)
{
    int e = blockIdx.x * blockDim.x + threadIdx.x;
    if (e >= nE) return;
    int c = ei[nE + e];
    int p = g_row_ptr[c] + atomicAdd(&g_cursor[c], 1);
    g_csr_src[p] = ei[e];
    g_csr_code[p] = et[e] * 3 + ed[e];
}

// ================= init: g_hh = fp16(emb1[at] + emb2[ch]) =================
__global__ void k_init(const int* __restrict__ at, const int* __restrict__ ch,
                       const float* __restrict__ e1, const float* __restrict__ e2, int n)
{
    int idx = blockIdx.x * blockDim.x + threadIdx.x;
    if (idx >= n * F4) return;
    int i = idx / F4, c = idx % F4;
    float4 a = ((const float4*)e1)[(size_t)at[i] * F4 + c];
    float4 b = ((const float4*)e2)[(size_t)ch[i] * F4 + c];
    uint2 o;
    o.x = pack_h2(a.x + b.x, a.y + b.y);
    o.y = pack_h2(a.z + b.z, a.w + b.w);
    ((uint2*)g_hh)[idx] = o;
}

// ===== merged per-layer prep: sconst | wprep | mkscale(+stat clear) =========
// block roles: [0, nsc) sconst ; [nsc, nsc+nwp) wprep ; [nsc+nwp, +2) mkscale
__global__ void k_prep(const float* __restrict__ ee1l, const float* __restrict__ ee2l,
                       const float* __restrict__ Wl,
                       const float* __restrict__ gamma, const float* __restrict__ beta,
                       int n, int nsc, int nwp, int domk)
{
    int blk = blockIdx.x, t = threadIdx.x;
    if (blk < nsc) {
        int i = blk * 256 + t;
        if (i < n) {
            float base = ee1l[4] + ee2l[0];
            int p0 = g_row_ptr[i], p1 = g_row_ptr[i + 1];
            for (int p = p0; p < p1; p++) {
                int code = g_csr_code[p];
                base += ee1l[code / 3] + ee2l[code % 3];
            }
            g_s[i] = base;
        }
    } else if (blk < nsc + nwp) {
        int idx = (blk - nsc) * 256 + t;
        if (idx < NPAD * W_U4ROW) {
            int nrow = idx / W_U4ROW, u = idx % W_U4ROW;
            unsigned w[4];
            #pragma unroll
            for (int j = 0; j < 4; j++) {
                int k0 = u * 8 + j * 2;
                float v0 = (nrow < EMBC && k0     < EMBC) ? Wl[(size_t)k0       * EMBC + nrow] : 0.f;
                float v1 = (nrow < EMBC && k0 + 1 < EMBC) ? Wl[(size_t)(k0 + 1) * EMBC + nrow] : 0.f;
                w[j] = pack_h2(v0, v1);
            }
            ((uint4*)g_wh)[idx] = make_uint4(w[0], w[1], w[2], w[3]);
        }
    } else {
        int i = (blk - nsc - nwp) * 256 + t;
        if (i < EMBC) {
            if (domk) {
                float inv_n = 1.f / (float)n;
                float mean = g_colsum[i] * inv_n;
                float var  = g_colsumsq[i] * inv_n - mean * mean;
                float sc = gamma[i] * rsqrtf(var + 1e-5f);
                g_scale[i] = sc;
                g_shift[i] = beta[i] - mean * sc;
            }
            g_colsum[i] = 0.f;      // same thread reads then clears: no race
            g_colsumsq[i] = 0.f;
        }
    }
}

// standalone mkscale for the final layer (stats consumed by pool, no clear needed)
__global__ void k_mkscale(const float* __restrict__ gamma, const float* __restrict__ beta, int n)
{
    int i = threadIdx.x + blockIdx.x * blockDim.x;
    if (i >= EMBC) return;
    float inv_n = 1.f / (float)n;
    float mean = g_colsum[i] * inv_n;
    float var  = g_colsumsq[i] * inv_n - mean * mean;
    float sc = gamma[i] * rsqrtf(var + 1e-5f);
    g_scale[i] = sc;
    g_shift[i] = beta[i] - mean * sc;
}

// ======= fused gather: aggh[i] = fp16( T(hh[i]) + sum_in T(hh[src]) ) =======
// mode 0: T = identity (layer 0). mode 1: T(x) = max(scale*x+shift, 0).
__global__ void k_gather2(int n, int mode)
{
    int idx = blockIdx.x * blockDim.x + threadIdx.x;
    if (idx >= n * GCH) return;
    int i = idx / GCH, c = idx % GCH;
    if (c >= F4) { ((uint2*)g_aggh)[idx] = make_uint2(0, 0); return; }
    int f = c * 4;
    float4 sc = make_float4(1.f, 1.f, 1.f, 1.f);
    float4 sh = make_float4(0.f, 0.f, 0.f, 0.f);
    if (mode) {
        sc = *(const float4*)&g_scale[f];
        sh = *(const float4*)&g_shift[f];
    }
    const uint2* HH = (const uint2*)g_hh;
    uint2 hx = HH[(size_t)i * F4 + c];
    float2 xa = unpack_h2(hx.x), xb = unpack_h2(hx.y);
    float v0, v1, v2, v3;
    if (mode) {
        v0 = fmaxf(fmaf(xa.x, sc.x, sh.x), 0.f); v1 = fmaxf(fmaf(xa.y, sc.y, sh.y), 0.f);
        v2 = fmaxf(fmaf(xb.x, sc.z, sh.z), 0.f); v3 = fmaxf(fmaf(xb.y, sc.w, sh.w), 0.f);
    } else { v0 = xa.x; v1 = xa.y; v2 = xb.x; v3 = xb.y; }
    int p0 = g_row_ptr[i], p1 = g_row_ptr[i + 1];
    for (int p = p0; p < p1; p++) {
        uint2 hy = HH[(size_t)g_csr_src[p] * F4 + c];
        float2 ya = unpack_h2(hy.x), yb = unpack_h2(hy.y);
        if (mode) {
            v0 += fmaxf(fmaf(ya.x, sc.x, sh.x), 0.f); v1 += fmaxf(fmaf(ya.y, sc.y, sh.y), 0.f);
            v2 += fmaxf(fmaf(yb.x, sc.z, sh.z), 0.f); v3 += fmaxf(fmaf(yb.y, sc.w, sh.w), 0.f);
        } else { v0 += ya.x; v1 += ya.y; v2 += yb.x; v3 += yb.y; }
    }
    uint2 o;
    o.x = pack_h2(v0, v1);
    o.y = pack_h2(v2, v3);
    ((uint2*)g_aggh)[idx] = o;
}

// ================= HMMA fp16 GEMM, k32 stages + fused column stats ==========
// D = Ah * Wh : per k32 tile, 2 sub-k16 rounds x 8 mma, ONE syncthreads.
// smem per buffer: A 128x80B = 10240 | B 64x80B = 5120 -> 15360 B.
// grid = (nb=5, mb); nb fastest so the 5 CTAs sharing an A-tile co-run (L2 reuse)
#define SBUF 15360

__global__ void __launch_bounds__(256)
k_gemm_mma(const float* __restrict__ bias, int M)
{
    __shared__ __align__(16) char smem[2 * SBUF];
    __shared__ float s_sum[64], s_sq[64];
    uint32_t sb = smem_u32(smem);
    int tid = threadIdx.x, lane = tid & 31, wid = tid >> 5;
    int wm = wid & 3, wn = wid >> 2;
    int m0 = blockIdx.y * 128, n0 = blockIdx.x * 64;
    const uint4* AGH = (const uint4*)g_aggh;   // 40 uint4 per row
    const uint4* WGH = (const uint4*)g_wh;     // 40 uint4 per row

    int arow = tid >> 1, apart = tid & 1;      // A: 2 uint4 per thread (32B)
    int brow = tid >> 2, bpart = tid & 3;      // B: 1 uint4 per thread (16B)

    float acc[2][4][4] = {};
    uint4 pa0, pa1, pb;

    {
        int arm = (m0 + arow < M);
        size_t abase = (size_t)(m0 + arow) * A_U4ROW + apart * 2;
        pa0 = arm ? AGH[abase]     : make_uint4(0,0,0,0);
        pa1 = arm ? AGH[abase + 1] : make_uint4(0,0,0,0);
        pb  = WGH[(size_t)(n0 + brow) * W_U4ROW + bpart];
        uint32_t base = sb;
        sts128(base + arow * 80 + apart * 32,      pa0);
        sts128(base + arow * 80 + apart * 32 + 16, pa1);
        sts128(base + 10240 + brow * 80 + bpart * 16, pb);
    }
    if (tid < 64) { s_sum[tid] = 0.f; s_sq[tid] = 0.f; }
    __syncthreads();

    uint32_t aoff = (uint32_t)((wm * 32 + (lane >> 2)) * 80 + (lane & 3) * 4);
    uint32_t boff = (uint32_t)((wn * 32 + (lane >> 2)) * 80 + (lane & 3) * 4);

    for (int kt = 0; kt < NKT; kt++) {
        int b = kt & 1;
        if (kt < NKT - 1) {
            int arm = (m0 + arow < M);
            size_t abase = (size_t)(m0 + arow) * A_U4ROW + (kt + 1) * 4 + apart * 2;
            pa0 = arm ? AGH[abase]     : make_uint4(0,0,0,0);
            pa1 = arm ? AGH[abase + 1] : make_uint4(0,0,0,0);
            pb  = WGH[(size_t)(n0 + brow) * W_U4ROW + (kt + 1) * 4 + bpart];
        }
        {
            uint32_t base = sb + b * SBUF;
            #pragma unroll
            for (int s = 0; s < 2; s++) {
                uint32_t AH = base + aoff + s * 32;
                uint32_t BH = base + 10240 + boff + s * 32;
                uint32_t af[2][4], bh[4][2];
                #pragma unroll
                for (int mt = 0; mt < 2; mt++) {
                    uint32_t r = AH + mt * 16 * 80;
                    af[mt][0] = lds32(r);       af[mt][1] = lds32(r + 8 * 80);
                    af[mt][2] = lds32(r + 16);  af[mt][3] = lds32(r + 8 * 80 + 16);
                }
                #pragma unroll
                for (int nt = 0; nt < 4; nt++) {
                    uint32_t r = BH + nt * 8 * 80;
                    bh[nt][0] = lds32(r);  bh[nt][1] = lds32(r + 16);
                }
                #pragma unroll
                for (int mt = 0; mt < 2; mt++)
                    #pragma unroll
                    for (int nt = 0; nt < 4; nt++)
                        mma_f16(acc[mt][nt], af[mt], bh[nt]);
            }
        }
        if (kt < NKT - 1) {
            uint32_t base = sb + (b ^ 1) * SBUF;
            sts128(base + arow * 80 + apart * 32,      pa0);
            sts128(base + arow * 80 + apart * 32 + 16, pa1);
            sts128(base + 10240 + brow * 80 + bpart * 16, pb);
        }
        __syncthreads();
    }

    // ---- epilogue: C + bias + s[row] -> g_hh (fp16 pair) ; fused stats -----
    unsigned* HO = (unsigned*)g_hh;
    float ls[4][2] = {}, lq[4][2] = {};
    #pragma unroll
    for (int mt = 0; mt < 2; mt++) {
        int row0 = m0 + wm * 32 + mt * 16 + (lane >> 2);
        int row1 = row0 + 8;
        float s0 = (row0 < M) ? g_s[row0] : 0.f;
        float s1 = (row1 < M) ? g_s[row1] : 0.f;
        #pragma unroll
        for (int nt = 0; nt < 4; nt++) {
            int col = n0 + wn * 32 + nt * 8 + (lane & 3) * 2;
            if (col < EMBC) {
                float b0 = bias[col], b1 = bias[col + 1];
                if (row0 < M) {
                    float v0 = acc[mt][nt][0] + b0 + s0;
                    float v1 = acc[mt][nt][1] + b1 + s0;
                    HO[(size_t)row0 * (EMBC / 2) + (col >> 1)] = pack_h2(v0, v1);
                    ls[nt][0] += v0; lq[nt][0] += v0 * v0;
                    ls[nt][1] += v1; lq[nt][1] += v1 * v1;
                }
                if (row1 < M) {
                    float v0 = acc[mt][nt][2] + b0 + s1;
                    float v1 = acc[mt][nt][3] + b1 + s1;
                    HO[(size_t)row1 * (EMBC / 2) + (col >> 1)] = pack_h2(v0, v1);
                    ls[nt][0] += v0; lq[nt][0] += v0 * v0;
                    ls[nt][1] += v1; lq[nt][1] += v1 * v1;
                }
            }
        }
    }
    #pragma unroll
    for (int nt = 0; nt < 4; nt++)
        #pragma unroll
        for (int jj = 0; jj < 2; jj++) {
            #pragma unroll
            for (int o = 4; o < 32; o <<= 1) {
                ls[nt][jj] += __shfl_xor_sync(0xffffffffu, ls[nt][jj], o);
                lq[nt][jj] += __shfl_xor_sync(0xffffffffu, lq[nt][jj], o);
            }
        }
    if (lane < 4) {
        #pragma unroll
        for (int nt = 0; nt < 4; nt++)
            #pragma unroll
            for (int jj = 0; jj < 2; jj++) {
                int ci = wn * 32 + nt * 8 + lane * 2 + jj;
                atomicAdd(&s_sum[ci], ls[nt][jj]);
                atomicAdd(&s_sq[ci],  lq[nt][jj]);
            }
    }
    __syncthreads();
    if (tid < 64) {
        int col = n0 + tid;
        if (col < EMBC) {
            atomicAdd(&g_colsum[col],   s_sum[tid]);
            atomicAdd(&g_colsumsq[col], s_sq[tid]);
        }
    }
}

// ================= mean pool with fused final BN (fp16 h) =================
__device__ __forceinline__ int lower_bound_i(const int* a, int n, int v)
{
    int lo = 0, hi = n;
    while (lo < hi) { int m = (lo + hi) >> 1; if (a[m] < v) lo = m + 1; else hi = m; }
    return lo;
}
__global__ void k_pool(const int* __restrict__ batch, int n)
{
    int g = blockIdx.x;
    int start = lower_bound_i(batch, n, g);
    int end   = lower_bound_i(batch, n, g + 1);
    int t = threadIdx.x;            // 160 threads, first 150 handle 2 cols each
    if (t >= EMBC / 2) return;
    const unsigned* HH = (const unsigned*)g_hh;
    float s0 = 0.f, s1 = 0.f;
    for (int i = start; i < end; i++) {
        float2 v = unpack_h2(HH[(size_t)i * (EMBC / 2) + t]);
        s0 += v.x; s1 += v.y;
    }
    float inv = 1.f / fmaxf((float)(end - start), 1.f);
    int f = t * 2;
    g_hg[(size_t)g * EMBC + f]     = fmaf(s0 * inv, g_scale[f],     g_shift[f]);
    g_hg[(size_t)g * EMBC + f + 1] = fmaf(s1 * inv, g_scale[f + 1], g_shift[f + 1]);
}

// ================= SIMT sgemm for head =================
template<int EPI>
__global__ __launch_bounds__(256)
void k_sgemm(int a_sel, float* a_ext, const float* __restrict__ B,
             int c_sel, float* c_ext, int M, int N, int K,
             const float* __restrict__ bias)
{
    const float* A = sel_ptr(a_sel, a_ext);
    float*       C = sel_ptr(c_sel, c_ext);
    __shared__ __align__(16) float As[16][64];
    __shared__ __align__(16) float Bs[16][64];
    int tid = threadIdx.x;
    int tx = tid & 15, ty = tid >> 4;
    int m0 = blockIdx.x * 64, n0 = blockIdx.y * 64;
    int am = tid >> 2, ak4 = tid & 3;
    int bk = tid >> 4, bn4 = tid & 15;
    float acc[4][4] = {};
    for (int kt = 0; kt < K; kt += 16) {
        float4 av = make_float4(0.f, 0.f, 0.f, 0.f);
        int arow = m0 + am, acol = kt + ak4 * 4;
        if (arow < M && acol + 4 <= K)
            av = *(const float4*)(A + (size_t)arow * K + acol);
        As[ak4 * 4 + 0][am] = av.x;
        As[ak4 * 4 + 1][am] = av.y;
        As[ak4 * 4 + 2][am] = av.z;
        As[ak4 * 4 + 3][am] = av.w;
        float4 bv = make_float4(0.f, 0.f, 0.f, 0.f);
        int brow = kt + bk, bcol = n0 + bn4 * 4;
        if (brow < K && bcol + 4 <= N)
            bv = *(const float4*)(B + (size_t)brow * N + bcol);
        *(float4*)&Bs[bk][bn4 * 4] = bv;
        __syncthreads();
        #pragma unroll
        for (int k = 0; k < 16; k++) {
            float4 a4 = *(const float4*)&As[k][ty * 4];
            float4 b4 = *(const float4*)&Bs[k][tx * 4];
            float ar[4] = {a4.x, a4.y, a4.z, a4.w};
            float br[4] = {b4.x, b4.y, b4.z, b4.w};
            #pragma unroll
            for (int i = 0; i < 4; i++)
                #pragma unroll
                for (int j = 0; j < 4; j++)
                    acc[i][j] += ar[i] * br[j];
        }
        __syncthreads();
    }
    float bb[4];
    #pragma unroll
    for (int j = 0; j < 4; j++) {
        int col = n0 + tx * 4 + j;
        bb[j] = (col < N) ? bias[col] : 0.f;
    }
    #pragma unroll
    for (int i = 0; i < 4; i++) {
        int row = m0 + ty * 4 + i;
        if (row >= M) continue;
        #pragma unroll
        for (int j = 0; j < 4; j++) {
            int col = n0 + tx * 4 + j;
            if (col >= N) continue;
            float v = acc[i][j] + bb[j];
            if (EPI == 1)
                v = (v > 0.f) ? v + log1pf(expf(-v)) : log1pf(expf(v));
            C[(size_t)row * N + col] = v;
        }
    }
}

__global__ void k_pred(const float* __restrict__ W2, const float* __restrict__ b2,
                       float* __restrict__ out)
{
    int g = blockIdx.x;
    int w = threadIdx.x >> 5;
    int lane = threadIdx.x & 31;
    float s = 0.f;
    #pragma unroll
    for (int q = 0; q < 4; q++) {
        int i = lane * 4 + q;
        s += g_t[(size_t)g * 128 + i] * W2[i * 2 + w];
    }
    #pragma unroll
    for (int o = 16; o > 0; o >>= 1) s += __shfl_xor_sync(0xffffffffu, s, o);
    if (lane == 0) out[g * 2 + w] = s + b2[w];
}

// ======================================================================
extern "C" void kernel_launch(void* const* d_in, const int* in_sizes, int n_in,
                              void* d_out, int out_size)
{
    const int*   atom_type = (const int*)d_in[0];
    const int*   chirality = (const int*)d_in[1];
    const int*   edge_index= (const int*)d_in[2];
    const int*   edge_type = (const int*)d_in[3];
    const int*   edge_dir  = (const int*)d_in[4];
    const int*   batch     = (const int*)d_in[5];
    const float* atom_emb1 = (const float*)d_in[6];
    const float* atom_emb2 = (const float*)d_in[7];
    const float* W         = (const float*)d_in[8];
    const float* b         = (const float*)d_in[9];
    const float* ee1       = (const float*)d_in[10];
    const float* ee2       = (const float*)d_in[11];
    const float* bn_gamma  = (const float*)d_in[12];
    const float* bn_beta   = (const float*)d_in[13];
    const float* feat_W    = (const float*)d_in[14];
    const float* feat_b    = (const float*)d_in[15];
    const float* head_W1   = (const float*)d_in[16];
    const float* head_b1   = (const float*)d_in[17];
    const float* head_W2   = (const float*)d_in[18];
    const float* head_b2   = (const float*)d_in[19];

    int N  = in_sizes[0];
    int E  = in_sizes[3];
    int NG = out_size / (256 + 2);

    float* out_f = (float*)d_out;
    float* hf    = out_f;
    float* pred  = out_f + (size_t)NG * 256;

    // CSR build
    k_zero2<<<(N + 255) / 256, 256>>>(N);
    k_count<<<(E + 255) / 256, 256>>>(edge_index, E);
    k_scan<<<1, 1024>>>(N);
    k_fill<<<(E + 255) / 256, 256>>>(edge_index, edge_type, edge_dir, E);

    // embedding init (fp16 h)
    k_init<<<(N * F4 + 255) / 256, 256>>>(atom_type, chirality, atom_emb1, atom_emb2, N);

    int nsc = (N + 255) / 256;
    int nwp = (NPAD * W_U4ROW + 255) / 256;
    dim3 ggrid(NPAD / 64, (N + 127) / 128);   // nb fastest -> A-tile L2 reuse
    for (int l = 0; l < NLAYER; l++) {
        const float* Wl   = W  + (size_t)l * EMBC * EMBC;
        const float* bl   = b  + (size_t)l * EMBC;
        const float* ee1l = ee1 + l * 5;
        const float* ee2l = ee2 + l * 3;
        const float* gm   = (l > 0) ? bn_gamma + (l - 1) * EMBC : bn_gamma;
        const float* bt   = (l > 0) ? bn_beta  + (l - 1) * EMBC : bn_beta;

        k_prep<<<nsc + nwp + 2, 256>>>(ee1l, ee2l, Wl, gm, bt, N, nsc, nwp, l > 0 ? 1 : 0);
        k_gather2<<<(N * GCH + 255) / 256, 256>>>(N, l > 0 ? 1 : 0);
        k_gemm_mma<<<ggrid, 256>>>(bl, N);
    }

    // final BN folded into pooling
    k_mkscale<<<2, 160>>>(bn_gamma + (NLAYER - 1) * EMBC, bn_beta + (NLAYER - 1) * EMBC, N);

    k_pool<<<NG, 160>>>(batch, N);
    {
        dim3 grid((NG + 63) / 64, (256 + 63) / 64);
        k_sgemm<0><<<grid, 256>>>(SEL_HG, nullptr, feat_W, SEL_EXT, hf,
                                  NG, 256, EMBC, feat_b);
    }
    {
        dim3 grid((NG + 63) / 64, (128 + 63) / 64);
        k_sgemm<1><<<grid, 256>>>(SEL_EXT, hf, head_W1, SEL_T, nullptr,
                                  NG, 128, 256, head_b1);
    }
    k_pred<<<NG, 64>>>(head_W2, head_b2, pred);
}

// round 15
// speedup vs baseline: 1.6503x; 1.0019x over previous
#include <cuda_runtime.h>
#include <cuda_bf16.h>
#include <cuda_fp16.h>
#include <math.h>
#include <stdint.h>

#define NMAX    100000
#define EMBC    300
#define F4      75
#define KP      320         // padded K: 10 k32 tiles
#define GCH     80          // uint2 chunks per aggh row: 320/4
#define A_U4ROW 40          // uint4s per fp16 A row: 320/8
#define W_U4ROW 40          // uint4s per fp16 W row: 320/8
#define NPAD    320         // padded N (output cols)
#define NKT     10          // k32 tiles
#define NGMAX   4096
#define NLAYER  5
#define EMAX    200000

// ---------------- device scratch ----------------
__device__ __align__(16) unsigned short g_aggh[(size_t)NMAX * KP];  // fp16 gathered A
__device__ __align__(16) unsigned short g_hh [(size_t)NMAX * EMBC]; // fp16 activations (pre-BN)
__device__ __align__(16) unsigned short g_wh[NPAD * KP];            // fp16 W^T
__device__ float g_s[NMAX];
__device__ float g_colsum[EMBC];
__device__ float g_colsumsq[EMBC];
__device__ float g_scale[EMBC];
__device__ float g_shift[EMBC];
__device__ __align__(16) float g_hg[(size_t)NGMAX * EMBC];
__device__ __align__(16) float g_t [(size_t)NGMAX * 128];
__device__ int g_deg[NMAX];
__device__ int g_cursor[NMAX];
__device__ int g_row_ptr[NMAX + 1];
__device__ int g_csr_src[EMAX];
__device__ int g_csr_code[EMAX];

#define SEL_EXT  0
#define SEL_HG   2
#define SEL_T    4
__device__ __forceinline__ float* sel_ptr(int sel, float* ext)
{
    switch (sel) {
        case SEL_HG: return g_hg;
        case SEL_T:  return g_t;
        default:     return ext;
    }
}

// ---------------- fp16 helpers ----------------
__device__ __forceinline__ unsigned pack_h2(float a, float b)
{
    __half2 p = __floats2half2_rn(a, b);
    return *reinterpret_cast<unsigned*>(&p);
}
__device__ __forceinline__ float2 unpack_h2(unsigned u)
{
    __half2 p = *reinterpret_cast<__half2*>(&u);
    return __half22float2(p);
}

// ---------------- smem helpers ----------------
__device__ __forceinline__ uint32_t smem_u32(const void* p)
{
    uint32_t a;
    asm("{ .reg .u64 t; cvta.to.shared.u64 t, %1; cvt.u32.u64 %0, t; }" : "=r"(a) : "l"(p));
    return a;
}
__device__ __forceinline__ void sts128(uint32_t addr, uint4 v)
{
    asm volatile("st.shared.v4.u32 [%0], {%1,%2,%3,%4};"
                 :: "r"(addr), "r"(v.x), "r"(v.y), "r"(v.z), "r"(v.w) : "memory");
}
__device__ __forceinline__ uint32_t lds32(uint32_t addr)
{
    uint32_t v;
    asm volatile("ld.shared.b32 %0, [%1];" : "=r"(v) : "r"(addr));
    return v;
}
__device__ __forceinline__ void mma_f16(float* c, const uint32_t* a, const uint32_t* b)
{
    asm volatile("mma.sync.aligned.m16n8k16.row.col.f32.f16.f16.f32 "
                 "{%0,%1,%2,%3}, {%4,%5,%6,%7}, {%8,%9}, {%0,%1,%2,%3};"
                 : "+f"(c[0]), "+f"(c[1]), "+f"(c[2]), "+f"(c[3])
                 : "r"(a[0]), "r"(a[1]), "r"(a[2]), "r"(a[3]), "r"(b[0]), "r"(b[1]));
}

// ================= CSR build =================
__global__ void k_zero2(int n)
{
    int i = blockIdx.x * blockDim.x + threadIdx.x;
    if (i < n) { g_deg[i] = 0; g_cursor[i] = 0; }
}
__global__ void k_count(const int* __restrict__ ei, int nE)
{
    int e = blockIdx.x * blockDim.x + threadIdx.x;
    if (e < nE) atomicAdd(&g_deg[ei[nE + e]], 1);
}
__global__ void k_scan(int n)
{
    __shared__ int sh[1024];
    int t = threadIdx.x;
    int chunk = (n + 1023) / 1024;
    int lo = t * chunk, hi = min(lo + chunk, n);
    int s = 0;
    for (int i = lo; i < hi; i++) s += g_deg[i];
    sh[t] = s;
    __syncthreads();
    for (int d = 1; d < 1024; d <<= 1) {
        int v = (t >= d) ? sh[t - d] : 0;
        __syncthreads();
        sh[t] += v;
        __syncthreads();
    }
    int run = sh[t] - s;
    for (int i = lo; i < hi; i++) { g_row_ptr[i] = run; run += g_deg[i]; }
    if (t == 1023) g_row_ptr[n] = run;
}
__global__ void k_fill(const int* __restrict__ ei, const int* __restrict__ et,
                       const int* __restrict__ ed, int nE)
{
    int e = blockIdx.x * blockDim.x + threadIdx.x;
    if (e >= nE) return;
    int c = ei[nE + e];
    int p = g_row_ptr[c] + atomicAdd(&g_cursor[c], 1);
    g_csr_src[p] = ei[e];
    g_csr_code[p] = et[e] * 3 + ed[e];
}

// ================= init: g_hh = fp16(emb1[at] + emb2[ch]) =================
__global__ void k_init(const int* __restrict__ at, const int* __restrict__ ch,
                       const float* __restrict__ e1, const float* __restrict__ e2, int n)
{
    int idx = blockIdx.x * blockDim.x + threadIdx.x;
    if (idx >= n * F4) return;
    int i = idx / F4, c = idx % F4;
    float4 a = ((const float4*)e1)[(size_t)at[i] * F4 + c];
    float4 b = ((const float4*)e2)[(size_t)ch[i] * F4 + c];
    uint2 o;
    o.x = pack_h2(a.x + b.x, a.y + b.y);
    o.y = pack_h2(a.z + b.z, a.w + b.w);
    ((uint2*)g_hh)[idx] = o;
}

// ===== merged per-layer prep: sconst | wprep | mkscale(+stat clear) =========
__global__ void k_prep(const float* __restrict__ ee1l, const float* __restrict__ ee2l,
                       const float* __restrict__ Wl,
                       const float* __restrict__ gamma, const float* __restrict__ beta,
                       int n, int nsc, int nwp, int domk)
{
    int blk = blockIdx.x, t = threadIdx.x;
    if (blk < nsc) {
        int i = blk * 256 + t;
        if (i < n) {
            float base = ee1l[4] + ee2l[0];
            int p0 = g_row_ptr[i], p1 = g_row_ptr[i + 1];
            for (int p = p0; p < p1; p++) {
                int code = g_csr_code[p];
                base += ee1l[code / 3] + ee2l[code % 3];
            }
            g_s[i] = base;
        }
    } else if (blk < nsc + nwp) {
        int idx = (blk - nsc) * 256 + t;
        if (idx < NPAD * W_U4ROW) {
            int nrow = idx / W_U4ROW, u = idx % W_U4ROW;
            unsigned w[4];
            #pragma unroll
            for (int j = 0; j < 4; j++) {
                int k0 = u * 8 + j * 2;
                float v0 = (nrow < EMBC && k0     < EMBC) ? Wl[(size_t)k0       * EMBC + nrow] : 0.f;
                float v1 = (nrow < EMBC && k0 + 1 < EMBC) ? Wl[(size_t)(k0 + 1) * EMBC + nrow] : 0.f;
                w[j] = pack_h2(v0, v1);
            }
            ((uint4*)g_wh)[idx] = make_uint4(w[0], w[1], w[2], w[3]);
        }
    } else {
        int i = (blk - nsc - nwp) * 256 + t;
        if (i < EMBC) {
            if (domk) {
                float inv_n = 1.f / (float)n;
                float mean = g_colsum[i] * inv_n;
                float var  = g_colsumsq[i] * inv_n - mean * mean;
                float sc = gamma[i] * rsqrtf(var + 1e-5f);
                g_scale[i] = sc;
                g_shift[i] = beta[i] - mean * sc;
            }
            g_colsum[i] = 0.f;
            g_colsumsq[i] = 0.f;
        }
    }
}

// standalone mkscale for the final layer
__global__ void k_mkscale(const float* __restrict__ gamma, const float* __restrict__ beta, int n)
{
    int i = threadIdx.x + blockIdx.x * blockDim.x;
    if (i >= EMBC) return;
    float inv_n = 1.f / (float)n;
    float mean = g_colsum[i] * inv_n;
    float var  = g_colsumsq[i] * inv_n - mean * mean;
    float sc = gamma[i] * rsqrtf(var + 1e-5f);
    g_scale[i] = sc;
    g_shift[i] = beta[i] - mean * sc;
}

// ======= fused gather: aggh[i] = fp16( T(hh[i]) + sum_in T(hh[src]) ) =======
// Each thread handles 2 uint2 chunks (c, c+40) of one row -> half the threads,
// half the index reads, MLP-2 neighbor loads. Chunk c+40 is padding for c>=35.
__global__ void k_gather3(int n, int mode)
{
    int idx = blockIdx.x * blockDim.x + threadIdx.x;
    if (idx >= n * 40) return;
    int i = idx / 40, c = idx % 40;
    int f0 = c * 4, f1 = (c + 40) * 4;
    int d1 = (c + 40) < F4;                   // second chunk holds data?
    float4 sc0 = make_float4(1.f, 1.f, 1.f, 1.f), sh0 = make_float4(0.f, 0.f, 0.f, 0.f);
    float4 sc1 = sc0, sh1 = sh0;
    if (mode) {
        sc0 = *(const float4*)&g_scale[f0];
        sh0 = *(const float4*)&g_shift[f0];
        if (d1) { sc1 = *(const float4*)&g_scale[f1]; sh1 = *(const float4*)&g_shift[f1]; }
    }
    const uint2* HH = (const uint2*)g_hh;
    size_t rb = (size_t)i * F4;
    uint2 hx0 = HH[rb + c];
    uint2 hx1 = d1 ? HH[rb + c + 40] : make_uint2(0, 0);
    float2 xa = unpack_h2(hx0.x), xb = unpack_h2(hx0.y);
    float2 xc = unpack_h2(hx1.x), xd = unpack_h2(hx1.y);
    float a0, a1, a2, a3, b0, b1, b2, b3;
    if (mode) {
        a0 = fmaxf(fmaf(xa.x, sc0.x, sh0.x), 0.f); a1 = fmaxf(fmaf(xa.y, sc0.y, sh0.y), 0.f);
        a2 = fmaxf(fmaf(xb.x, sc0.z, sh0.z), 0.f); a3 = fmaxf(fmaf(xb.y, sc0.w, sh0.w), 0.f);
        b0 = fmaxf(fmaf(xc.x, sc1.x, sh1.x), 0.f); b1 = fmaxf(fmaf(xc.y, sc1.y, sh1.y), 0.f);
        b2 = fmaxf(fmaf(xd.x, sc1.z, sh1.z), 0.f); b3 = fmaxf(fmaf(xd.y, sc1.w, sh1.w), 0.f);
    } else {
        a0 = xa.x; a1 = xa.y; a2 = xb.x; a3 = xb.y;
        b0 = xc.x; b1 = xc.y; b2 = xd.x; b3 = xd.y;
    }
    int p0 = g_row_ptr[i], p1 = g_row_ptr[i + 1];
    for (int p = p0; p < p1; p++) {
        size_t sbase = (size_t)g_csr_src[p] * F4;
        uint2 hy0 = HH[sbase + c];
        uint2 hy1 = d1 ? HH[sbase + c + 40] : make_uint2(0, 0);
        float2 ya = unpack_h2(hy0.x), yb = unpack_h2(hy0.y);
        float2 yc = unpack_h2(hy1.x), yd = unpack_h2(hy1.y);
        if (mode) {
            a0 += fmaxf(fmaf(ya.x, sc0.x, sh0.x), 0.f); a1 += fmaxf(fmaf(ya.y, sc0.y, sh0.y), 0.f);
            a2 += fmaxf(fmaf(yb.x, sc0.z, sh0.z), 0.f); a3 += fmaxf(fmaf(yb.y, sc0.w, sh0.w), 0.f);
            b0 += fmaxf(fmaf(yc.x, sc1.x, sh1.x), 0.f); b1 += fmaxf(fmaf(yc.y, sc1.y, sh1.y), 0.f);
            b2 += fmaxf(fmaf(yd.x, sc1.z, sh1.z), 0.f); b3 += fmaxf(fmaf(yd.y, sc1.w, sh1.w), 0.f);
        } else {
            a0 += ya.x; a1 += ya.y; a2 += yb.x; a3 += yb.y;
            b0 += yc.x; b1 += yc.y; b2 += yd.x; b3 += yd.y;
        }
    }
    uint2* AO = (uint2*)g_aggh;
    size_t ob = (size_t)i * GCH;
    uint2 o0, o1;
    o0.x = pack_h2(a0, a1); o0.y = pack_h2(a2, a3);
    o1.x = d1 ? pack_h2(b0, b1) : 0u;
    o1.y = d1 ? pack_h2(b2, b3) : 0u;
    AO[ob + c]      = o0;
    AO[ob + c + 40] = o1;
}

// ================= HMMA fp16 GEMM, k32 stages + fused column stats ==========
#define SBUF 15360

__global__ void __launch_bounds__(256)
k_gemm_mma(const float* __restrict__ bias, int M)
{
    __shared__ __align__(16) char smem[2 * SBUF];
    __shared__ float s_sum[64], s_sq[64];
    uint32_t sb = smem_u32(smem);
    int tid = threadIdx.x, lane = tid & 31, wid = tid >> 5;
    int wm = wid & 3, wn = wid >> 2;
    int m0 = blockIdx.y * 128, n0 = blockIdx.x * 64;
    const uint4* AGH = (const uint4*)g_aggh;
    const uint4* WGH = (const uint4*)g_wh;

    int arow = tid >> 1, apart = tid & 1;
    int brow = tid >> 2, bpart = tid & 3;

    float acc[2][4][4] = {};
    uint4 pa0, pa1, pb;

    {
        int arm = (m0 + arow < M);
        size_t abase = (size_t)(m0 + arow) * A_U4ROW + apart * 2;
        pa0 = arm ? AGH[abase]     : make_uint4(0,0,0,0);
        pa1 = arm ? AGH[abase + 1] : make_uint4(0,0,0,0);
        pb  = WGH[(size_t)(n0 + brow) * W_U4ROW + bpart];
        uint32_t base = sb;
        sts128(base + arow * 80 + apart * 32,      pa0);
        sts128(base + arow * 80 + apart * 32 + 16, pa1);
        sts128(base + 10240 + brow * 80 + bpart * 16, pb);
    }
    if (tid < 64) { s_sum[tid] = 0.f; s_sq[tid] = 0.f; }
    __syncthreads();

    uint32_t aoff = (uint32_t)((wm * 32 + (lane >> 2)) * 80 + (lane & 3) * 4);
    uint32_t boff = (uint32_t)((wn * 32 + (lane >> 2)) * 80 + (lane & 3) * 4);

    for (int kt = 0; kt < NKT; kt++) {
        int b = kt & 1;
        if (kt < NKT - 1) {
            int arm = (m0 + arow < M);
            size_t abase = (size_t)(m0 + arow) * A_U4ROW + (kt + 1) * 4 + apart * 2;
            pa0 = arm ? AGH[abase]     : make_uint4(0,0,0,0);
            pa1 = arm ? AGH[abase + 1] : make_uint4(0,0,0,0);
            pb  = WGH[(size_t)(n0 + brow) * W_U4ROW + (kt + 1) * 4 + bpart];
        }
        {
            uint32_t base = sb + b * SBUF;
            #pragma unroll
            for (int s = 0; s < 2; s++) {
                uint32_t AH = base + aoff + s * 32;
                uint32_t BH = base + 10240 + boff + s * 32;
                uint32_t af[2][4], bh[4][2];
                #pragma unroll
                for (int mt = 0; mt < 2; mt++) {
                    uint32_t r = AH + mt * 16 * 80;
                    af[mt][0] = lds32(r);       af[mt][1] = lds32(r + 8 * 80);
                    af[mt][2] = lds32(r + 16);  af[mt][3] = lds32(r + 8 * 80 + 16);
                }
                #pragma unroll
                for (int nt = 0; nt < 4; nt++) {
                    uint32_t r = BH + nt * 8 * 80;
                    bh[nt][0] = lds32(r);  bh[nt][1] = lds32(r + 16);
                }
                #pragma unroll
                for (int mt = 0; mt < 2; mt++)
                    #pragma unroll
                    for (int nt = 0; nt < 4; nt++)
                        mma_f16(acc[mt][nt], af[mt], bh[nt]);
            }
        }
        if (kt < NKT - 1) {
            uint32_t base = sb + (b ^ 1) * SBUF;
            sts128(base + arow * 80 + apart * 32,      pa0);
            sts128(base + arow * 80 + apart * 32 + 16, pa1);
            sts128(base + 10240 + brow * 80 + bpart * 16, pb);
        }
        __syncthreads();
    }

    // ---- epilogue: C + bias + s[row] -> g_hh (fp16 pair) ; fused stats -----
    unsigned* HO = (unsigned*)g_hh;
    float ls[4][2] = {}, lq[4][2] = {};
    #pragma unroll
    for (int mt = 0; mt < 2; mt++) {
        int row0 = m0 + wm * 32 + mt * 16 + (lane >> 2);
        int row1 = row0 + 8;
        float s0 = (row0 < M) ? g_s[row0] : 0.f;
        float s1 = (row1 < M) ? g_s[row1] : 0.f;
        #pragma unroll
        for (int nt = 0; nt < 4; nt++) {
            int col = n0 + wn * 32 + nt * 8 + (lane & 3) * 2;
            if (col < EMBC) {
                float b0 = bias[col], b1 = bias[col + 1];
                if (row0 < M) {
                    float v0 = acc[mt][nt][0] + b0 + s0;
                    float v1 = acc[mt][nt][1] + b1 + s0;
                    HO[(size_t)row0 * (EMBC / 2) + (col >> 1)] = pack_h2(v0, v1);
                    ls[nt][0] += v0; lq[nt][0] += v0 * v0;
                    ls[nt][1] += v1; lq[nt][1] += v1 * v1;
                }
                if (row1 < M) {
                    float v0 = acc[mt][nt][2] + b0 + s1;
                    float v1 = acc[mt][nt][3] + b1 + s1;
                    HO[(size_t)row1 * (EMBC / 2) + (col >> 1)] = pack_h2(v0, v1);
                    ls[nt][0] += v0; lq[nt][0] += v0 * v0;
                    ls[nt][1] += v1; lq[nt][1] += v1 * v1;
                }
            }
        }
    }
    #pragma unroll
    for (int nt = 0; nt < 4; nt++)
        #pragma unroll
        for (int jj = 0; jj < 2; jj++) {
            #pragma unroll
            for (int o = 4; o < 32; o <<= 1) {
                ls[nt][jj] += __shfl_xor_sync(0xffffffffu, ls[nt][jj], o);
                lq[nt][jj] += __shfl_xor_sync(0xffffffffu, lq[nt][jj], o);
            }
        }
    if (lane < 4) {
        #pragma unroll
        for (int nt = 0; nt < 4; nt++)
            #pragma unroll
            for (int jj = 0; jj < 2; jj++) {
                int ci = wn * 32 + nt * 8 + lane * 2 + jj;
                atomicAdd(&s_sum[ci], ls[nt][jj]);
                atomicAdd(&s_sq[ci],  lq[nt][jj]);
            }
    }
    __syncthreads();
    if (tid < 64) {
        int col = n0 + tid;
        if (col < EMBC) {
            atomicAdd(&g_colsum[col],   s_sum[tid]);
            atomicAdd(&g_colsumsq[col], s_sq[tid]);
        }
    }
}

// ================= mean pool with fused final BN (fp16 h) =================
__device__ __forceinline__ int lower_bound_i(const int* a, int n, int v)
{
    int lo = 0, hi = n;
    while (lo < hi) { int m = (lo + hi) >> 1; if (a[m] < v) lo = m + 1; else hi = m; }
    return lo;
}
__global__ void k_pool(const int* __restrict__ batch, int n)
{
    int g = blockIdx.x;
    int start = lower_bound_i(batch, n, g);
    int end   = lower_bound_i(batch, n, g + 1);
    int t = threadIdx.x;
    if (t >= EMBC / 2) return;
    const unsigned* HH = (const unsigned*)g_hh;
    float s0 = 0.f, s1 = 0.f;
    for (int i = start; i < end; i++) {
        float2 v = unpack_h2(HH[(size_t)i * (EMBC / 2) + t]);
        s0 += v.x; s1 += v.y;
    }
    float inv = 1.f / fmaxf((float)(end - start), 1.f);
    int f = t * 2;
    g_hg[(size_t)g * EMBC + f]     = fmaf(s0 * inv, g_scale[f],     g_shift[f]);
    g_hg[(size_t)g * EMBC + f + 1] = fmaf(s1 * inv, g_scale[f + 1], g_shift[f + 1]);
}

// ================= SIMT sgemm for head =================
template<int EPI>
__global__ __launch_bounds__(256)
void k_sgemm(int a_sel, float* a_ext, const float* __restrict__ B,
             int c_sel, float* c_ext, int M, int N, int K,
             const float* __restrict__ bias)
{
    const float* A = sel_ptr(a_sel, a_ext);
    float*       C = sel_ptr(c_sel, c_ext);
    __shared__ __align__(16) float As[16][64];
    __shared__ __align__(16) float Bs[16][64];
    int tid = threadIdx.x;
    int tx = tid & 15, ty = tid >> 4;
    int m0 = blockIdx.x * 64, n0 = blockIdx.y * 64;
    int am = tid >> 2, ak4 = tid & 3;
    int bk = tid >> 4, bn4 = tid & 15;
    float acc[4][4] = {};
    for (int kt = 0; kt < K; kt += 16) {
        float4 av = make_float4(0.f, 0.f, 0.f, 0.f);
        int arow = m0 + am, acol = kt + ak4 * 4;
        if (arow < M && acol + 4 <= K)
            av = *(const float4*)(A + (size_t)arow * K + acol);
        As[ak4 * 4 + 0][am] = av.x;
        As[ak4 * 4 + 1][am] = av.y;
        As[ak4 * 4 + 2][am] = av.z;
        As[ak4 * 4 + 3][am] = av.w;
        float4 bv = make_float4(0.f, 0.f, 0.f, 0.f);
        int brow = kt + bk, bcol = n0 + bn4 * 4;
        if (brow < K && bcol + 4 <= N)
            bv = *(const float4*)(B + (size_t)brow * N + bcol);
        *(float4*)&Bs[bk][bn4 * 4] = bv;
        __syncthreads();
        #pragma unroll
        for (int k = 0; k < 16; k++) {
            float4 a4 = *(const float4*)&As[k][ty * 4];
            float4 b4 = *(const float4*)&Bs[k][tx * 4];
            float ar[4] = {a4.x, a4.y, a4.z, a4.w};
            float br[4] = {b4.x, b4.y, b4.z, b4.w};
            #pragma unroll
            for (int i = 0; i < 4; i++)
                #pragma unroll
                for (int j = 0; j < 4; j++)
                    acc[i][j] += ar[i] * br[j];
        }
        __syncthreads();
    }
    float bb[4];
    #pragma unroll
    for (int j = 0; j < 4; j++) {
        int col = n0 + tx * 4 + j;
        bb[j] = (col < N) ? bias[col] : 0.f;
    }
    #pragma unroll
    for (int i = 0; i < 4; i++) {
        int row = m0 + ty * 4 + i;
        if (row >= M) continue;
        #pragma unroll
        for (int j = 0; j < 4; j++) {
            int col = n0 + tx * 4 + j;
            if (col >= N) continue;
            float v = acc[i][j] + bb[j];
            if (EPI == 1)
                v = (v > 0.f) ? v + log1pf(expf(-v)) : log1pf(expf(v));
            C[(size_t)row * N + col] = v;
        }
    }
}

__global__ void k_pred(const float* __restrict__ W2, const float* __restrict__ b2,
                       float* __restrict__ out)
{
    int g = blockIdx.x;
    int w = threadIdx.x >> 5;
    int lane = threadIdx.x & 31;
    float s = 0.f;
    #pragma unroll
    for (int q = 0; q < 4; q++) {
        int i = lane * 4 + q;
        s += g_t[(size_t)g * 128 + i] * W2[i * 2 + w];
    }
    #pragma unroll
    for (int o = 16; o > 0; o >>= 1) s += __shfl_xor_sync(0xffffffffu, s, o);
    if (lane == 0) out[g * 2 + w] = s + b2[w];
}

// ======================================================================
extern "C" void kernel_launch(void* const* d_in, const int* in_sizes, int n_in,
                              void* d_out, int out_size)
{
    const int*   atom_type = (const int*)d_in[0];
    const int*   chirality = (const int*)d_in[1];
    const int*   edge_index= (const int*)d_in[2];
    const int*   edge_type = (const int*)d_in[3];
    const int*   edge_dir  = (const int*)d_in[4];
    const int*   batch     = (const int*)d_in[5];
    const float* atom_emb1 = (const float*)d_in[6];
    const float* atom_emb2 = (const float*)d_in[7];
    const float* W         = (const float*)d_in[8];
    const float* b         = (const float*)d_in[9];
    const float* ee1       = (const float*)d_in[10];
    const float* ee2       = (const float*)d_in[11];
    const float* bn_gamma  = (const float*)d_in[12];
    const float* bn_beta   = (const float*)d_in[13];
    const float* feat_W    = (const float*)d_in[14];
    const float* feat_b    = (const float*)d_in[15];
    const float* head_W1   = (const float*)d_in[16];
    const float* head_b1   = (const float*)d_in[17];
    const float* head_W2   = (const float*)d_in[18];
    const float* head_b2   = (const float*)d_in[19];

    int N  = in_sizes[0];
    int E  = in_sizes[3];
    int NG = out_size / (256 + 2);

    float* out_f = (float*)d_out;
    float* hf    = out_f;
    float* pred  = out_f + (size_t)NG * 256;

    // CSR build
    k_zero2<<<(N + 255) / 256, 256>>>(N);
    k_count<<<(E + 255) / 256, 256>>>(edge_index, E);
    k_scan<<<1, 1024>>>(N);
    k_fill<<<(E + 255) / 256, 256>>>(edge_index, edge_type, edge_dir, E);

    // embedding init (fp16 h)
    k_init<<<(N * F4 + 255) / 256, 256>>>(atom_type, chirality, atom_emb1, atom_emb2, N);

    int nsc = (N + 255) / 256;
    int nwp = (NPAD * W_U4ROW + 255) / 256;
    dim3 ggrid(NPAD / 64, (N + 127) / 128);
    for (int l = 0; l < NLAYER; l++) {
        const float* Wl   = W  + (size_t)l * EMBC * EMBC;
        const float* bl   = b  + (size_t)l * EMBC;
        const float* ee1l = ee1 + l * 5;
        const float* ee2l = ee2 + l * 3;
        const float* gm   = (l > 0) ? bn_gamma + (l - 1) * EMBC : bn_gamma;
        const float* bt   = (l > 0) ? bn_beta  + (l - 1) * EMBC : bn_beta;

        k_prep<<<nsc + nwp + 2, 256>>>(ee1l, ee2l, Wl, gm, bt, N, nsc, nwp, l > 0 ? 1 : 0);
        k_gather3<<<(N * 40 + 255) / 256, 256>>>(N, l > 0 ? 1 : 0);
        k_gemm_mma<<<ggrid, 256>>>(bl, N);
    }

    // final BN folded into pooling
    k_mkscale<<<2, 160>>>(bn_gamma + (NLAYER - 1) * EMBC, bn_beta + (NLAYER - 1) * EMBC, N);

    k_pool<<<NG, 160>>>(batch, N);
    {
        dim3 grid((NG + 63) / 64, (256 + 63) / 64);
        k_sgemm<0><<<grid, 256>>>(SEL_HG, nullptr, feat_W, SEL_EXT, hf,
                                  NG, 256, EMBC, feat_b);
    }
    {
        dim3 grid((NG + 63) / 64, (128 + 63) / 64);
        k_sgemm<1><<<grid, 256>>>(SEL_EXT, hf, head_W1, SEL_T, nullptr,
                                  NG, 128, 256, head_b1);
    }
    k_pred<<<NG, 64>>>(head_W2, head_b2, pred);
}

// round 16
// speedup vs baseline: 1.6686x; 1.0111x over previous
#include <cuda_runtime.h>
#include <cuda_bf16.h>
#include <cuda_fp16.h>
#include <math.h>
#include <stdint.h>

#define NMAX    100000
#define EMBC    300
#define F4      75
#define KP      320         // padded K: 10 k32 tiles
#define GCH     80          // uint2 chunks per aggh row: 320/4
#define A_U4ROW 40          // uint4s per fp16 A row: 320/8
#define W_U4ROW 40          // uint4s per fp16 W row: 320/8
#define NPAD    320         // padded N (output cols)
#define NKT     10          // k32 tiles
#define NGMAX   4096
#define NLAYER  5
#define EMAX    200000

// ---------------- device scratch ----------------
__device__ __align__(16) unsigned short g_aggh[(size_t)NMAX * KP];  // fp16 gathered A
__device__ __align__(16) unsigned short g_hh [(size_t)NMAX * EMBC]; // fp16 activations (pre-BN)
__device__ __align__(16) unsigned short g_wh[NPAD * KP];            // fp16 W^T
__device__ float g_s[NMAX];
__device__ float g_colsum[EMBC];
__device__ float g_colsumsq[EMBC];
__device__ float g_scale[EMBC];
__device__ float g_shift[EMBC];
__device__ __align__(16) float g_hg[(size_t)NGMAX * EMBC];
__device__ __align__(16) float g_t [(size_t)NGMAX * 128];
__device__ int g_deg[NMAX];
__device__ int g_cursor[NMAX];
__device__ int g_row_ptr[NMAX + 1];
__device__ int g_csr_src[EMAX];
__device__ int g_csr_code[EMAX];

#define SEL_EXT  0
#define SEL_HG   2
#define SEL_T    4
__device__ __forceinline__ float* sel_ptr(int sel, float* ext)
{
    switch (sel) {
        case SEL_HG: return g_hg;
        case SEL_T:  return g_t;
        default:     return ext;
    }
}

// ---------------- fp16 helpers ----------------
__device__ __forceinline__ unsigned pack_h2(float a, float b)
{
    __half2 p = __floats2half2_rn(a, b);
    return *reinterpret_cast<unsigned*>(&p);
}
__device__ __forceinline__ float2 unpack_h2(unsigned u)
{
    __half2 p = *reinterpret_cast<__half2*>(&u);
    return __half22float2(p);
}

// ---------------- smem helpers ----------------
__device__ __forceinline__ uint32_t smem_u32(const void* p)
{
    uint32_t a;
    asm("{ .reg .u64 t; cvta.to.shared.u64 t, %1; cvt.u32.u64 %0, t; }" : "=r"(a) : "l"(p));
    return a;
}
__device__ __forceinline__ void sts128(uint32_t addr, uint4 v)
{
    asm volatile("st.shared.v4.u32 [%0], {%1,%2,%3,%4};"
                 :: "r"(addr), "r"(v.x), "r"(v.y), "r"(v.z), "r"(v.w) : "memory");
}
__device__ __forceinline__ uint32_t lds32(uint32_t addr)
{
    uint32_t v;
    asm volatile("ld.shared.b32 %0, [%1];" : "=r"(v) : "r"(addr));
    return v;
}
__device__ __forceinline__ void mma_f16(float* c, const uint32_t* a, const uint32_t* b)
{
    asm volatile("mma.sync.aligned.m16n8k16.row.col.f32.f16.f16.f32 "
                 "{%0,%1,%2,%3}, {%4,%5,%6,%7}, {%8,%9}, {%0,%1,%2,%3};"
                 : "+f"(c[0]), "+f"(c[1]), "+f"(c[2]), "+f"(c[3])
                 : "r"(a[0]), "r"(a[1]), "r"(a[2]), "r"(a[3]), "r"(b[0]), "r"(b[1]));
}

// ================= CSR build =================
__global__ void k_zero2(int n)
{
    int i = blockIdx.x * blockDim.x + threadIdx.x;
    if (i < n) { g_deg[i] = 0; g_cursor[i] = 0; }
}
__global__ void k_count(const int* __restrict__ ei, int nE)
{
    int e = blockIdx.x * blockDim.x + threadIdx.x;
    if (e < nE) atomicAdd(&g_deg[ei[nE + e]], 1);
}
__global__ void k_scan(int n)
{
    __shared__ int sh[1024];
    int t = threadIdx.x;
    int chunk = (n + 1023) / 1024;
    int lo = t * chunk, hi = min(lo + chunk, n);
    int s = 0;
    for (int i = lo; i < hi; i++) s += g_deg[i];
    sh[t] = s;
    __syncthreads();
    for (int d = 1; d < 1024; d <<= 1) {
        int v = (t >= d) ? sh[t - d] : 0;
        __syncthreads();
        sh[t] += v;
        __syncthreads();
    }
    int run = sh[t] - s;
    for (int i = lo; i < hi; i++) { g_row_ptr[i] = run; run += g_deg[i]; }
    if (t == 1023) g_row_ptr[n] = run;
}
__global__ void k_fill(const int* __restrict__ ei, const int* __restrict__ et,
                       const int* __restrict__ ed, int nE)
{
    int e = blockIdx.x * blockDim.x + threadIdx.x;
    if (e >= nE) return;
    int c = ei[nE + e];
    int p = g_row_ptr[c] + atomicAdd(&g_cursor[c], 1);
    g_csr_src[p] = ei[e];
    g_csr_code[p] = et[e] * 3 + ed[e];
}

// ================= init: g_hh = fp16(emb1[at] + emb2[ch]) =================
__global__ void k_init(const int* __restrict__ at, const int* __restrict__ ch,
                       const float* __restrict__ e1, const float* __restrict__ e2, int n)
{
    int idx = blockIdx.x * blockDim.x + threadIdx.x;
    if (idx >= n * F4) return;
    int i = idx / F4, c = idx % F4;
    float4 a = ((const float4*)e1)[(size_t)at[i] * F4 + c];
    float4 b = ((const float4*)e2)[(size_t)ch[i] * F4 + c];
    uint2 o;
    o.x = pack_h2(a.x + b.x, a.y + b.y);
    o.y = pack_h2(a.z + b.z, a.w + b.w);
    ((uint2*)g_hh)[idx] = o;
}

// ===== merged per-layer prep: sconst | wprep | mkscale(+stat clear) =========
__global__ void k_prep(const float* __restrict__ ee1l, const float* __restrict__ ee2l,
                       const float* __restrict__ Wl,
                       const float* __restrict__ gamma, const float* __restrict__ beta,
                       int n, int nsc, int nwp, int domk)
{
    int blk = blockIdx.x, t = threadIdx.x;
    if (blk < nsc) {
        int i = blk * 256 + t;
        if (i < n) {
            float base = ee1l[4] + ee2l[0];
            int p0 = g_row_ptr[i], p1 = g_row_ptr[i + 1];
            for (int p = p0; p < p1; p++) {
                int code = g_csr_code[p];
                base += ee1l[code / 3] + ee2l[code % 3];
            }
            g_s[i] = base;
        }
    } else if (blk < nsc + nwp) {
        int idx = (blk - nsc) * 256 + t;
        if (idx < NPAD * W_U4ROW) {
            int nrow = idx / W_U4ROW, u = idx % W_U4ROW;
            unsigned w[4];
            #pragma unroll
            for (int j = 0; j < 4; j++) {
                int k0 = u * 8 + j * 2;
                float v0 = (nrow < EMBC && k0     < EMBC) ? Wl[(size_t)k0       * EMBC + nrow] : 0.f;
                float v1 = (nrow < EMBC && k0 + 1 < EMBC) ? Wl[(size_t)(k0 + 1) * EMBC + nrow] : 0.f;
                w[j] = pack_h2(v0, v1);
            }
            ((uint4*)g_wh)[idx] = make_uint4(w[0], w[1], w[2], w[3]);
        }
    } else {
        int i = (blk - nsc - nwp) * 256 + t;
        if (i < EMBC) {
            if (domk) {
                float inv_n = 1.f / (float)n;
                float mean = g_colsum[i] * inv_n;
                float var  = g_colsumsq[i] * inv_n - mean * mean;
                float sc = gamma[i] * rsqrtf(var + 1e-5f);
                g_scale[i] = sc;
                g_shift[i] = beta[i] - mean * sc;
            }
            g_colsum[i] = 0.f;
            g_colsumsq[i] = 0.f;
        }
    }
}

// standalone mkscale for the final layer
__global__ void k_mkscale(const float* __restrict__ gamma, const float* __restrict__ beta, int n)
{
    int i = threadIdx.x + blockIdx.x * blockDim.x;
    if (i >= EMBC) return;
    float inv_n = 1.f / (float)n;
    float mean = g_colsum[i] * inv_n;
    float var  = g_colsumsq[i] * inv_n - mean * mean;
    float sc = gamma[i] * rsqrtf(var + 1e-5f);
    g_scale[i] = sc;
    g_shift[i] = beta[i] - mean * sc;
}

// ======= fused gather: aggh[i] = fp16( T(hh[i]) + sum_in T(hh[src]) ) =======
__global__ void k_gather3(int n, int mode)
{
    int idx = blockIdx.x * blockDim.x + threadIdx.x;
    if (idx >= n * 40) return;
    int i = idx / 40, c = idx % 40;
    int f0 = c * 4, f1 = (c + 40) * 4;
    int d1 = (c + 40) < F4;
    float4 sc0 = make_float4(1.f, 1.f, 1.f, 1.f), sh0 = make_float4(0.f, 0.f, 0.f, 0.f);
    float4 sc1 = sc0, sh1 = sh0;
    if (mode) {
        sc0 = *(const float4*)&g_scale[f0];
        sh0 = *(const float4*)&g_shift[f0];
        if (d1) { sc1 = *(const float4*)&g_scale[f1]; sh1 = *(const float4*)&g_shift[f1]; }
    }
    const uint2* HH = (const uint2*)g_hh;
    size_t rb = (size_t)i * F4;
    uint2 hx0 = HH[rb + c];
    uint2 hx1 = d1 ? HH[rb + c + 40] : make_uint2(0, 0);
    float2 xa = unpack_h2(hx0.x), xb = unpack_h2(hx0.y);
    float2 xc = unpack_h2(hx1.x), xd = unpack_h2(hx1.y);
    float a0, a1, a2, a3, b0, b1, b2, b3;
    if (mode) {
        a0 = fmaxf(fmaf(xa.x, sc0.x, sh0.x), 0.f); a1 = fmaxf(fmaf(xa.y, sc0.y, sh0.y), 0.f);
        a2 = fmaxf(fmaf(xb.x, sc0.z, sh0.z), 0.f); a3 = fmaxf(fmaf(xb.y, sc0.w, sh0.w), 0.f);
        b0 = fmaxf(fmaf(xc.x, sc1.x, sh1.x), 0.f); b1 = fmaxf(fmaf(xc.y, sc1.y, sh1.y), 0.f);
        b2 = fmaxf(fmaf(xd.x, sc1.z, sh1.z), 0.f); b3 = fmaxf(fmaf(xd.y, sc1.w, sh1.w), 0.f);
    } else {
        a0 = xa.x; a1 = xa.y; a2 = xb.x; a3 = xb.y;
        b0 = xc.x; b1 = xc.y; b2 = xd.x; b3 = xd.y;
    }
    int p0 = g_row_ptr[i], p1 = g_row_ptr[i + 1];
    for (int p = p0; p < p1; p++) {
        size_t sbase = (size_t)g_csr_src[p] * F4;
        uint2 hy0 = HH[sbase + c];
        uint2 hy1 = d1 ? HH[sbase + c + 40] : make_uint2(0, 0);
        float2 ya = unpack_h2(hy0.x), yb = unpack_h2(hy0.y);
        float2 yc = unpack_h2(hy1.x), yd = unpack_h2(hy1.y);
        if (mode) {
            a0 += fmaxf(fmaf(ya.x, sc0.x, sh0.x), 0.f); a1 += fmaxf(fmaf(ya.y, sc0.y, sh0.y), 0.f);
            a2 += fmaxf(fmaf(yb.x, sc0.z, sh0.z), 0.f); a3 += fmaxf(fmaf(yb.y, sc0.w, sh0.w), 0.f);
            b0 += fmaxf(fmaf(yc.x, sc1.x, sh1.x), 0.f); b1 += fmaxf(fmaf(yc.y, sc1.y, sh1.y), 0.f);
            b2 += fmaxf(fmaf(yd.x, sc1.z, sh1.z), 0.f); b3 += fmaxf(fmaf(yd.y, sc1.w, sh1.w), 0.f);
        } else {
            a0 += ya.x; a1 += ya.y; a2 += yb.x; a3 += yb.y;
            b0 += yc.x; b1 += yc.y; b2 += yd.x; b3 += yd.y;
        }
    }
    uint2* AO = (uint2*)g_aggh;
    size_t ob = (size_t)i * GCH;
    uint2 o0, o1;
    o0.x = pack_h2(a0, a1); o0.y = pack_h2(a2, a3);
    o1.x = d1 ? pack_h2(b0, b1) : 0u;
    o1.y = d1 ? pack_h2(b2, b3) : 0u;
    AO[ob + c]      = o0;
    AO[ob + c + 40] = o1;
}

// ========== HMMA fp16 GEMM: CTA 256x64, warp 32x64, k32 stages ==============
// smem per buffer: A 256x80B = 20480 | B 64x80B = 5120 -> 25600 B.
#define SBUF 25600

__global__ void __launch_bounds__(256)
k_gemm_mma(const float* __restrict__ bias, int M)
{
    __shared__ __align__(16) char smem[2 * SBUF];
    __shared__ float s_sum[64], s_sq[64];
    uint32_t sb = smem_u32(smem);
    int tid = threadIdx.x, lane = tid & 31, wid = tid >> 5;
    int m0 = blockIdx.y * 256, n0 = blockIdx.x * 64;
    const uint4* AGH = (const uint4*)g_aggh;
    const uint4* WGH = (const uint4*)g_wh;

    int arow = tid >> 1, apart = tid & 1;      // A: rows arow and arow+128, 32B each
    int brow = tid >> 2, bpart = tid & 3;      // B: 1 uint4 per thread

    float acc[2][8][4] = {};
    uint4 pa0a, pa0b, pa1a, pa1b, pb;

    {
        int r0 = m0 + arow, r1 = m0 + arow + 128;
        size_t ab0 = (size_t)r0 * A_U4ROW + apart * 2;
        size_t ab1 = (size_t)r1 * A_U4ROW + apart * 2;
        pa0a = (r0 < M) ? AGH[ab0]     : make_uint4(0,0,0,0);
        pa0b = (r0 < M) ? AGH[ab0 + 1] : make_uint4(0,0,0,0);
        pa1a = (r1 < M) ? AGH[ab1]     : make_uint4(0,0,0,0);
        pa1b = (r1 < M) ? AGH[ab1 + 1] : make_uint4(0,0,0,0);
        pb   = WGH[(size_t)(n0 + brow) * W_U4ROW + bpart];
        uint32_t base = sb;
        sts128(base + arow * 80 + apart * 32,              pa0a);
        sts128(base + arow * 80 + apart * 32 + 16,         pa0b);
        sts128(base + (arow + 128) * 80 + apart * 32,      pa1a);
        sts128(base + (arow + 128) * 80 + apart * 32 + 16, pa1b);
        sts128(base + 20480 + brow * 80 + bpart * 16, pb);
    }
    if (tid < 64) { s_sum[tid] = 0.f; s_sq[tid] = 0.f; }
    __syncthreads();

    uint32_t aoff = (uint32_t)((wid * 32 + (lane >> 2)) * 80 + (lane & 3) * 4);
    uint32_t boff = (uint32_t)((lane >> 2) * 80 + (lane & 3) * 4);

    for (int kt = 0; kt < NKT; kt++) {
        int b = kt & 1;
        if (kt < NKT - 1) {
            int r0 = m0 + arow, r1 = m0 + arow + 128;
            size_t ab0 = (size_t)r0 * A_U4ROW + (kt + 1) * 4 + apart * 2;
            size_t ab1 = (size_t)r1 * A_U4ROW + (kt + 1) * 4 + apart * 2;
            pa0a = (r0 < M) ? AGH[ab0]     : make_uint4(0,0,0,0);
            pa0b = (r0 < M) ? AGH[ab0 + 1] : make_uint4(0,0,0,0);
            pa1a = (r1 < M) ? AGH[ab1]     : make_uint4(0,0,0,0);
            pa1b = (r1 < M) ? AGH[ab1 + 1] : make_uint4(0,0,0,0);
            pb   = WGH[(size_t)(n0 + brow) * W_U4ROW + (kt + 1) * 4 + bpart];
        }
        {
            uint32_t base = sb + b * SBUF;
            #pragma unroll
            for (int s = 0; s < 2; s++) {
                uint32_t AH = base + aoff + s * 32;
                uint32_t BH = base + 20480 + boff + s * 32;
                uint32_t af[2][4], bh[8][2];
                #pragma unroll
                for (int mt = 0; mt < 2; mt++) {
                    uint32_t r = AH + mt * 16 * 80;
                    af[mt][0] = lds32(r);       af[mt][1] = lds32(r + 8 * 80);
                    af[mt][2] = lds32(r + 16);  af[mt][3] = lds32(r + 8 * 80 + 16);
                }
                #pragma unroll
                for (int nt = 0; nt < 8; nt++) {
                    uint32_t r = BH + nt * 8 * 80;
                    bh[nt][0] = lds32(r);  bh[nt][1] = lds32(r + 16);
                }
                #pragma unroll
                for (int mt = 0; mt < 2; mt++)
                    #pragma unroll
                    for (int nt = 0; nt < 8; nt++)
                        mma_f16(acc[mt][nt], af[mt], bh[nt]);
            }
        }
        if (kt < NKT - 1) {
            uint32_t base = sb + (b ^ 1) * SBUF;
            sts128(base + arow * 80 + apart * 32,              pa0a);
            sts128(base + arow * 80 + apart * 32 + 16,         pa0b);
            sts128(base + (arow + 128) * 80 + apart * 32,      pa1a);
            sts128(base + (arow + 128) * 80 + apart * 32 + 16, pa1b);
            sts128(base + 20480 + brow * 80 + bpart * 16, pb);
        }
        __syncthreads();
    }

    // ---- epilogue: C + bias + s[row] -> g_hh (fp16 pair) ; fused stats -----
    unsigned* HO = (unsigned*)g_hh;
    float ls[8][2] = {}, lq[8][2] = {};
    #pragma unroll
    for (int mt = 0; mt < 2; mt++) {
        int row0 = m0 + wid * 32 + mt * 16 + (lane >> 2);
        int row1 = row0 + 8;
        float s0 = (row0 < M) ? g_s[row0] : 0.f;
        float s1 = (row1 < M) ? g_s[row1] : 0.f;
        #pragma unroll
        for (int nt = 0; nt < 8; nt++) {
            int col = n0 + nt * 8 + (lane & 3) * 2;
            if (col < EMBC) {
                float b0 = bias[col], b1 = bias[col + 1];
                if (row0 < M) {
                    float v0 = acc[mt][nt][0] + b0 + s0;
                    float v1 = acc[mt][nt][1] + b1 + s0;
                    HO[(size_t)row0 * (EMBC / 2) + (col >> 1)] = pack_h2(v0, v1);
                    ls[nt][0] += v0; lq[nt][0] += v0 * v0;
                    ls[nt][1] += v1; lq[nt][1] += v1 * v1;
                }
                if (row1 < M) {
                    float v0 = acc[mt][nt][2] + b0 + s1;
                    float v1 = acc[mt][nt][3] + b1 + s1;
                    HO[(size_t)row1 * (EMBC / 2) + (col >> 1)] = pack_h2(v0, v1);
                    ls[nt][0] += v0; lq[nt][0] += v0 * v0;
                    ls[nt][1] += v1; lq[nt][1] += v1 * v1;
                }
            }
        }
    }
    #pragma unroll
    for (int nt = 0; nt < 8; nt++)
        #pragma unroll
        for (int jj = 0; jj < 2; jj++) {
            #pragma unroll
            for (int o = 4; o < 32; o <<= 1) {
                ls[nt][jj] += __shfl_xor_sync(0xffffffffu, ls[nt][jj], o);
                lq[nt][jj] += __shfl_xor_sync(0xffffffffu, lq[nt][jj], o);
            }
        }
    if (lane < 4) {
        #pragma unroll
        for (int nt = 0; nt < 8; nt++)
            #pragma unroll
            for (int jj = 0; jj < 2; jj++) {
                int ci = nt * 8 + lane * 2 + jj;
                atomicAdd(&s_sum[ci], ls[nt][jj]);
                atomicAdd(&s_sq[ci],  lq[nt][jj]);
            }
    }
    __syncthreads();
    if (tid < 64) {
        int col = n0 + tid;
        if (col < EMBC) {
            atomicAdd(&g_colsum[col],   s_sum[tid]);
            atomicAdd(&g_colsumsq[col], s_sq[tid]);
        }
    }
}

// ================= mean pool with fused final BN (fp16 h) =================
__device__ __forceinline__ int lower_bound_i(const int* a, int n, int v)
{
    int lo = 0, hi = n;
    while (lo < hi) { int m = (lo + hi) >> 1; if (a[m] < v) lo = m + 1; else hi = m; }
    return lo;
}
__global__ void k_pool(const int* __restrict__ batch, int n)
{
    int g = blockIdx.x;
    int start = lower_bound_i(batch, n, g);
    int end   = lower_bound_i(batch, n, g + 1);
    int t = threadIdx.x;
    if (t >= EMBC / 2) return;
    const unsigned* HH = (const unsigned*)g_hh;
    float s0 = 0.f, s1 = 0.f;
    for (int i = start; i < end; i++) {
        float2 v = unpack_h2(HH[(size_t)i * (EMBC / 2) + t]);
        s0 += v.x; s1 += v.y;
    }
    float inv = 1.f / fmaxf((float)(end - start), 1.f);
    int f = t * 2;
    g_hg[(size_t)g * EMBC + f]     = fmaf(s0 * inv, g_scale[f],     g_shift[f]);
    g_hg[(size_t)g * EMBC + f + 1] = fmaf(s1 * inv, g_scale[f + 1], g_shift[f + 1]);
}

// ================= SIMT sgemm for head =================
template<int EPI>
__global__ __launch_bounds__(256)
void k_sgemm(int a_sel, float* a_ext, const float* __restrict__ B,
             int c_sel, float* c_ext, int M, int N, int K,
             const float* __restrict__ bias)
{
    const float* A = sel_ptr(a_sel, a_ext);
    float*       C = sel_ptr(c_sel, c_ext);
    __shared__ __align__(16) float As[16][64];
    __shared__ __align__(16) float Bs[16][64];
    int tid = threadIdx.x;
    int tx = tid & 15, ty = tid >> 4;
    int m0 = blockIdx.x * 64, n0 = blockIdx.y * 64;
    int am = tid >> 2, ak4 = tid & 3;
    int bk = tid >> 4, bn4 = tid & 15;
    float acc[4][4] = {};
    for (int kt = 0; kt < K; kt += 16) {
        float4 av = make_float4(0.f, 0.f, 0.f, 0.f);
        int arow = m0 + am, acol = kt + ak4 * 4;
        if (arow < M && acol + 4 <= K)
            av = *(const float4*)(A + (size_t)arow * K + acol);
        As[ak4 * 4 + 0][am] = av.x;
        As[ak4 * 4 + 1][am] = av.y;
        As[ak4 * 4 + 2][am] = av.z;
        As[ak4 * 4 + 3][am] = av.w;
        float4 bv = make_float4(0.f, 0.f, 0.f, 0.f);
        int brow = kt + bk, bcol = n0 + bn4 * 4;
        if (brow < K && bcol + 4 <= N)
            bv = *(const float4*)(B + (size_t)brow * N + bcol);
        *(float4*)&Bs[bk][bn4 * 4] = bv;
        __syncthreads();
        #pragma unroll
        for (int k = 0; k < 16; k++) {
            float4 a4 = *(const float4*)&As[k][ty * 4];
            float4 b4 = *(const float4*)&Bs[k][tx * 4];
            float ar[4] = {a4.x, a4.y, a4.z, a4.w};
            float br[4] = {b4.x, b4.y, b4.z, b4.w};
            #pragma unroll
            for (int i = 0; i < 4; i++)
                #pragma unroll
                for (int j = 0; j < 4; j++)
                    acc[i][j] += ar[i] * br[j];
        }
        __syncthreads();
    }
    float bb[4];
    #pragma unroll
    for (int j = 0; j < 4; j++) {
        int col = n0 + tx * 4 + j;
        bb[j] = (col < N) ? bias[col] : 0.f;
    }
    #pragma unroll
    for (int i = 0; i < 4; i++) {
        int row = m0 + ty * 4 + i;
        if (row >= M) continue;
        #pragma unroll
        for (int j = 0; j < 4; j++) {
            int col = n0 + tx * 4 + j;
            if (col >= N) continue;
            float v = acc[i][j] + bb[j];
            if (EPI == 1)
                v = (v > 0.f) ? v + log1pf(expf(-v)) : log1pf(expf(v));
            C[(size_t)row * N + col] = v;
        }
    }
}

__global__ void k_pred(const float* __restrict__ W2, const float* __restrict__ b2,
                       float* __restrict__ out)
{
    int g = blockIdx.x;
    int w = threadIdx.x >> 5;
    int lane = threadIdx.x & 31;
    float s = 0.f;
    #pragma unroll
    for (int q = 0; q < 4; q++) {
        int i = lane * 4 + q;
        s += g_t[(size_t)g * 128 + i] * W2[i * 2 + w];
    }
    #pragma unroll
    for (int o = 16; o > 0; o >>= 1) s += __shfl_xor_sync(0xffffffffu, s, o);
    if (lane == 0) out[g * 2 + w] = s + b2[w];
}

// ======================================================================
extern "C" void kernel_launch(void* const* d_in, const int* in_sizes, int n_in,
                              void* d_out, int out_size)
{
    const int*   atom_type = (const int*)d_in[0];
    const int*   chirality = (const int*)d_in[1];
    const int*   edge_index= (const int*)d_in[2];
    const int*   edge_type = (const int*)d_in[3];
    const int*   edge_dir  = (const int*)d_in[4];
    const int*   batch     = (const int*)d_in[5];
    const float* atom_emb1 = (const float*)d_in[6];
    const float* atom_emb2 = (const float*)d_in[7];
    const float* W         = (const float*)d_in[8];
    const float* b         = (const float*)d_in[9];
    const float* ee1       = (const float*)d_in[10];
    const float* ee2       = (const float*)d_in[11];
    const float* bn_gamma  = (const float*)d_in[12];
    const float* bn_beta   = (const float*)d_in[13];
    const float* feat_W    = (const float*)d_in[14];
    const float* feat_b    = (const float*)d_in[15];
    const float* head_W1   = (const float*)d_in[16];
    const float* head_b1   = (const float*)d_in[17];
    const float* head_W2   = (const float*)d_in[18];
    const float* head_b2   = (const float*)d_in[19];

    int N  = in_sizes[0];
    int E  = in_sizes[3];
    int NG = out_size / (256 + 2);

    float* out_f = (float*)d_out;
    float* hf    = out_f;
    float* pred  = out_f + (size_t)NG * 256;

    // CSR build
    k_zero2<<<(N + 255) / 256, 256>>>(N);
    k_count<<<(E + 255) / 256, 256>>>(edge_index, E);
    k_scan<<<1, 1024>>>(N);
    k_fill<<<(E + 255) / 256, 256>>>(edge_index, edge_type, edge_dir, E);

    // embedding init (fp16 h)
    k_init<<<(N * F4 + 255) / 256, 256>>>(atom_type, chirality, atom_emb1, atom_emb2, N);

    int nsc = (N + 255) / 256;
    int nwp = (NPAD * W_U4ROW + 255) / 256;
    dim3 ggrid(NPAD / 64, (N + 255) / 256);
    for (int l = 0; l < NLAYER; l++) {
        const float* Wl   = W  + (size_t)l * EMBC * EMBC;
        const float* bl   = b  + (size_t)l * EMBC;
        const float* ee1l = ee1 + l * 5;
        const float* ee2l = ee2 + l * 3;
        const float* gm   = (l > 0) ? bn_gamma + (l - 1) * EMBC : bn_gamma;
        const float* bt   = (l > 0) ? bn_beta  + (l - 1) * EMBC : bn_beta;

        k_prep<<<nsc + nwp + 2, 256>>>(ee1l, ee2l, Wl, gm, bt, N, nsc, nwp, l > 0 ? 1 : 0);
        k_gather3<<<(N * 40 + 255) / 256, 256>>>(N, l > 0 ? 1 : 0);
        k_gemm_mma<<<ggrid, 256>>>(bl, N);
    }

    // final BN folded into pooling
    k_mkscale<<<2, 160>>>(bn_gamma + (NLAYER - 1) * EMBC, bn_beta + (NLAYER - 1) * EMBC, N);

    k_pool<<<NG, 160>>>(batch, N);
    {
        dim3 grid((NG + 63) / 64, (256 + 63) / 64);
        k_sgemm<0><<<grid, 256>>>(SEL_HG, nullptr, feat_W, SEL_EXT, hf,
                                  NG, 256, EMBC, feat_b);
    }
    {
        dim3 grid((NG + 63) / 64, (128 + 63) / 64);
        k_sgemm<1><<<grid, 256>>>(SEL_EXT, hf, head_W1, SEL_T, nullptr,
                                  NG, 128, 256, head_b1);
    }
    k_pred<<<NG, 64>>>(head_W2, head_b2, pred);
}